// round 14
// baseline (speedup 1.0000x reference)
#include <cuda_runtime.h>
#include <cuda_fp16.h>
#include <math.h>
#include <stdint.h>

#define B_   4
#define S_   512
#define E_   768
#define H_   12
#define D_   64
#define FF_  3072
#define L_   12
#define NTOK (B_*S_)     // 2048
#define BH   (B_*H_)     // 48
#define E3_  (3*E_)      // 2304

#define SCALE_INV 0.03608439182435161f   // 1/sqrt(768), applied AFTER softmax

// ---------------- scratch (static __device__, no allocation) ----------------
__device__ __half g_h[NTOK*E_];
__device__ __half g_q[BH*S_*D_];        // [z][s][d]
__device__ __half g_k[BH*S_*D_];        // [z][s][d]
__device__ __half g_v[BH*D_*S_];        // [z][d][s]  (transposed for PV)
__device__ __half g_merged[NTOK*E_];
__device__ float  g_oproj[NTOK*E_];
__device__ float  g_r1[NTOK*E_];
__device__ __half g_f[NTOK*E_];
__device__ __half g_ff[NTOK*FF_];
__device__ float  g_f2[NTOK*E_];
__device__ float  g_x[NTOK*E_];
// fp16 + transposed weight copies ([N][K] K-major per layer)
__device__ __half g_Wqkv_t[(size_t)L_*E_*E3_];
__device__ __half g_Wp_t[(size_t)L_*E_*E_];
__device__ __half g_W1_t[(size_t)L_*E_*FF_];
__device__ __half g_W2_t[(size_t)L_*FF_*E_];

// ---------------- helpers ----------------
__device__ __forceinline__ void mma_f16(float* c, const uint32_t* a, const uint32_t* b) {
    asm volatile(
        "mma.sync.aligned.m16n8k16.row.col.f32.f16.f16.f32 "
        "{%0,%1,%2,%3}, {%4,%5,%6,%7}, {%8,%9}, {%0,%1,%2,%3};"
        : "+f"(c[0]), "+f"(c[1]), "+f"(c[2]), "+f"(c[3])
        : "r"(a[0]), "r"(a[1]), "r"(a[2]), "r"(a[3]), "r"(b[0]), "r"(b[1]));
}

__device__ __forceinline__ void cp_async16(void* smem, const void* gmem) {
    uint32_t s = (uint32_t)__cvta_generic_to_shared(smem);
    asm volatile("cp.async.cg.shared.global [%0], [%1], 16;\n" :: "r"(s), "l"(gmem));
}
__device__ __forceinline__ void cp_commit() {
    asm volatile("cp.async.commit_group;\n");
}
template<int N> __device__ __forceinline__ void cp_wait() {
    asm volatile("cp.async.wait_group %0;\n" :: "n"(N));
}

__device__ __forceinline__ float gelu_exact(float x) {
    return 0.5f * x * (1.0f + erff(x * 0.7071067811865476f));
}

// ---------------- fp16 tensor-core GEMM, cp.async 3-stage, BK=64 ------------
// C = A[M,K](half) @ Bt[N,K](half, pre-transposed) + bias(f32).
// ACT: 0 plain f32 out; 1 gelu -> half out; 2 qkv-split scatter (half).
#define GH_STAGE 36864                       // 18432 A + 18432 B
#define GH_SMEM  (3 * GH_STAGE)              // 110592

template<int ACT>
__global__ void __launch_bounds__(256, 2) gemm_h(
    const __half* __restrict__ A, const __half* __restrict__ Bt,
    const float* __restrict__ bias, void* __restrict__ Cout,
    int M, int N, int K,
    __half* __restrict__ qp, __half* __restrict__ kp, __half* __restrict__ vp)
{
    extern __shared__ char smem[];
    const int tid  = threadIdx.x;
    const int lane = tid & 31;
    const int warp = tid >> 5;
    const int wm = (warp & 1) * 64;           // WRM=2
    const int wn = (warp >> 1) * 32;          // WRN=4
    const int bm = blockIdx.y * 128;
    const int bn = blockIdx.x * 128;
    const int niter = K / 64;

    float acc[4][4][4] = {};

    auto issue = [&](int s) {
        char* st = smem + (s % 3) * GH_STAGE;
        int k0 = s * 64;
        #pragma unroll
        for (int r = 0; r < 4; r++) {
            int ch = tid + r * 256;
            int row = ch >> 3, kq = ch & 7;
            cp_async16(st + row * 144 + kq * 16,
                       &A[(size_t)(bm + row) * K + k0 + kq * 8]);
            cp_async16(st + 18432 + row * 144 + kq * 16,
                       &Bt[(size_t)(bn + row) * K + k0 + kq * 8]);
        }
    };

    auto compute = [&](int buf) {
        const uint32_t* Ab = (const uint32_t*)(smem + buf * GH_STAGE);
        const uint32_t* Bb = (const uint32_t*)(smem + buf * GH_STAGE + 18432);
        #pragma unroll
        for (int kk = 0; kk < 4; kk++) {            // four k16 slices per BK=64
            int c0 = kk * 8 + (lane & 3);
            uint32_t af[4][4];
            #pragma unroll
            for (int i = 0; i < 4; i++) {
                const uint32_t* p = &Ab[(wm + i * 16 + (lane >> 2)) * 36 + c0];
                af[i][0] = p[0];
                af[i][1] = p[288];      // +8 rows * 36 words
                af[i][2] = p[4];        // +8 halves
                af[i][3] = p[292];
            }
            uint32_t bf[4][2];
            #pragma unroll
            for (int j = 0; j < 4; j++) {
                const uint32_t* p = &Bb[(wn + j * 8 + (lane >> 2)) * 36 + c0];
                bf[j][0] = p[0];
                bf[j][1] = p[4];        // k+8
            }
            #pragma unroll
            for (int i = 0; i < 4; i++)
                #pragma unroll
                for (int j = 0; j < 4; j++)
                    mma_f16(acc[i][j], af[i], bf[j]);
        }
    };

    #pragma unroll
    for (int s = 0; s < 2; s++) { if (s < niter) issue(s); cp_commit(); }
    for (int it = 0; it < niter; ++it) {
        cp_wait<1>();
        __syncthreads();
        if (it + 2 < niter) issue(it + 2);
        cp_commit();
        compute(it % 3);
    }

    // ---- epilogue ----
    #pragma unroll
    for (int i = 0; i < 4; i++) {
        #pragma unroll
        for (int j = 0; j < 4; j++) {
            int row = bm + wm + i * 16 + (lane >> 2);
            int col = bn + wn + j * 8 + (lane & 3) * 2;
            float2 bv = make_float2(0.f, 0.f);
            if (bias) bv = *(const float2*)&bias[col];
            float o[2][2] = {{acc[i][j][0] + bv.x, acc[i][j][1] + bv.y},
                             {acc[i][j][2] + bv.x, acc[i][j][3] + bv.y}};
            if (ACT == 0) {
                float* C = (float*)Cout;
                *(float2*)&C[(size_t)row * N + col]       = make_float2(o[0][0], o[0][1]);
                *(float2*)&C[(size_t)(row + 8) * N + col] = make_float2(o[1][0], o[1][1]);
            } else if (ACT == 1) {
                __half* C = (__half*)Cout;
                *(__half2*)&C[(size_t)row * N + col] =
                    __floats2half2_rn(gelu_exact(o[0][0]), gelu_exact(o[0][1]));
                *(__half2*)&C[(size_t)(row + 8) * N + col] =
                    __floats2half2_rn(gelu_exact(o[1][0]), gelu_exact(o[1][1]));
            } else {
                #pragma unroll
                for (int r = 0; r < 2; r++) {
                    int rr = row + r * 8;
                    int b = rr >> 9, s = rr & 511;
                    #pragma unroll
                    for (int cc = 0; cc < 2; cc++) {
                        int n = col + cc;
                        int c3 = n % 3, hd = n / 3;
                        int h = hd >> 6, d = hd & 63;
                        int z = b * H_ + h;
                        __half val = __float2half_rn(o[r][cc]);
                        if (c3 == 0)      qp[((size_t)z * S_ + s) * D_ + d] = val;
                        else if (c3 == 1) kp[((size_t)z * S_ + s) * D_ + d] = val;
                        else              vp[((size_t)z * D_ + d) * S_ + s] = val;
                    }
                }
            }
        }
    }
}

// ---------------- BM=64 x BN=128, BK=64 variant (N=768 GEMMs: 192 CTAs) -----
// 128 threads, warp tile 32x64 (WRM=2, WRN=2). Plain f32+bias epilogue.
#define G64_STAGE 27648                      // A 64*144 + B 128*144
#define G64_SMEM  (3 * G64_STAGE)            // 82944

__global__ void __launch_bounds__(128, 2) gemm_h64(
    const __half* __restrict__ A, const __half* __restrict__ Bt,
    const float* __restrict__ bias, float* __restrict__ C,
    int M, int N, int K)
{
    extern __shared__ char smem[];
    const int tid  = threadIdx.x;
    const int lane = tid & 31;
    const int warp = tid >> 5;
    const int wm = (warp & 1) * 32;           // WRM=2
    const int wn = (warp >> 1) * 64;          // WRN=2
    const int bm = blockIdx.y * 64;
    const int bn = blockIdx.x * 128;
    const int niter = K / 64;

    float acc[2][8][4] = {};

    auto issue = [&](int s) {
        char* st = smem + (s % 3) * G64_STAGE;
        int k0 = s * 64;
        #pragma unroll
        for (int r = 0; r < 4; r++) {
            int ch = tid + r * 128;
            int row = ch >> 3, kq = ch & 7;
            cp_async16(st + row * 144 + kq * 16,
                       &A[(size_t)(bm + row) * K + k0 + kq * 8]);
        }
        #pragma unroll
        for (int r = 0; r < 8; r++) {
            int ch = tid + r * 128;
            int row = ch >> 3, kq = ch & 7;
            cp_async16(st + 9216 + row * 144 + kq * 16,
                       &Bt[(size_t)(bn + row) * K + k0 + kq * 8]);
        }
    };

    auto compute = [&](int buf) {
        const uint32_t* Ab = (const uint32_t*)(smem + buf * G64_STAGE);
        const uint32_t* Bb = (const uint32_t*)(smem + buf * G64_STAGE + 9216);
        #pragma unroll
        for (int kk = 0; kk < 4; kk++) {
            int c0 = kk * 8 + (lane & 3);
            uint32_t af[2][4];
            #pragma unroll
            for (int i = 0; i < 2; i++) {
                const uint32_t* p = &Ab[(wm + i * 16 + (lane >> 2)) * 36 + c0];
                af[i][0] = p[0];
                af[i][1] = p[288];
                af[i][2] = p[4];
                af[i][3] = p[292];
            }
            uint32_t bf[8][2];
            #pragma unroll
            for (int j = 0; j < 8; j++) {
                const uint32_t* p = &Bb[(wn + j * 8 + (lane >> 2)) * 36 + c0];
                bf[j][0] = p[0];
                bf[j][1] = p[4];
            }
            #pragma unroll
            for (int i = 0; i < 2; i++)
                #pragma unroll
                for (int j = 0; j < 8; j++)
                    mma_f16(acc[i][j], af[i], bf[j]);
        }
    };

    #pragma unroll
    for (int s = 0; s < 2; s++) { if (s < niter) issue(s); cp_commit(); }
    for (int it = 0; it < niter; ++it) {
        cp_wait<1>();
        __syncthreads();
        if (it + 2 < niter) issue(it + 2);
        cp_commit();
        compute(it % 3);
    }

    #pragma unroll
    for (int i = 0; i < 2; i++) {
        #pragma unroll
        for (int j = 0; j < 8; j++) {
            int row = bm + wm + i * 16 + (lane >> 2);
            int col = bn + wn + j * 8 + (lane & 3) * 2;
            float2 bv = *(const float2*)&bias[col];
            *(float2*)&C[(size_t)row * N + col] =
                make_float2(acc[i][j][0] + bv.x, acc[i][j][1] + bv.y);
            *(float2*)&C[(size_t)(row + 8) * N + col] =
                make_float2(acc[i][j][2] + bv.x, acc[i][j][3] + bv.y);
        }
    }
}

// ---------------- flash attention v2 (R12: 64 q-rows, 128 threads) ----------
#define FA2_SMEM 64512     // Q 9216 + 3*K 27648 + 3*V 27648 bytes

__global__ void __launch_bounds__(128, 2) flash2_kernel(
    const __half* __restrict__ q, const __half* __restrict__ k,
    const __half* __restrict__ vt, __half* __restrict__ merged)
{
    extern __shared__ __half hs[];
    __half* Qs = hs;                     // 64 x 72
    __half* Ks = hs + 4608;              // 3 x (64 x 72)
    __half* Vs = hs + 4 * 4608;          // 3 x (64 x 72)

    const int tid = threadIdx.x, lane = tid & 31, warp = tid >> 5;
    const int z = blockIdx.y, q0 = blockIdx.x * 64;
    const __half* qg = q  + (size_t)z * S_ * D_ + (size_t)q0 * D_;
    const __half* kg = k  + (size_t)z * S_ * D_;
    const __half* vg = vt + (size_t)z * D_ * S_;

    auto loadKV = [&](int t) {
        __half* dk = Ks + (t % 3) * 4608;
        __half* dv = Vs + (t % 3) * 4608;
        const __half* sk = kg + (size_t)t * 64 * 64;
        #pragma unroll
        for (int r = 0; r < 4; r++) {
            int ch = tid + r * 128;
            int row = ch >> 3, c = ch & 7;
            cp_async16(dk + row * 72 + c * 8, sk + row * 64 + c * 8);
            cp_async16(dv + row * 72 + c * 8, vg + row * 512 + t * 64 + c * 8);
        }
    };

    #pragma unroll
    for (int r = 0; r < 4; r++) {
        int ch = tid + r * 128;
        int row = ch >> 3, c = ch & 7;
        cp_async16(Qs + row * 72 + c * 8, qg + row * 64 + c * 8);
    }
    loadKV(0); cp_commit();
    loadKV(1); cp_commit();

    uint32_t qa[4][4];
    float Oacc[8][4] = {};
    float m0 = -INFINITY, m1 = -INFINITY, l0 = 0.f, l1 = 0.f;

    const int r0 = warp * 16 + (lane >> 2);
    const int ccol = (lane & 3) * 2;

    for (int t = 0; t < 8; t++) {
        cp_wait<1>();
        __syncthreads();
        if (t == 0) {
            #pragma unroll
            for (int kc = 0; kc < 4; kc++) {
                qa[kc][0] = *(const uint32_t*)(Qs + r0 * 72 + kc * 16 + ccol);
                qa[kc][1] = *(const uint32_t*)(Qs + (r0 + 8) * 72 + kc * 16 + ccol);
                qa[kc][2] = *(const uint32_t*)(Qs + r0 * 72 + kc * 16 + 8 + ccol);
                qa[kc][3] = *(const uint32_t*)(Qs + (r0 + 8) * 72 + kc * 16 + 8 + ccol);
            }
        }
        if (t + 2 < 8) loadKV(t + 2);
        cp_commit();

        const __half* Kt = Ks + (t % 3) * 4608;
        const __half* Vb = Vs + (t % 3) * 4608;

        float sacc[8][4] = {};
        #pragma unroll
        for (int kc = 0; kc < 4; kc++) {
            uint32_t kb[8][2];
            #pragma unroll
            for (int nt = 0; nt < 8; nt++) {
                const __half* pk = Kt + (nt * 8 + (lane >> 2)) * 72 + kc * 16 + ccol;
                kb[nt][0] = *(const uint32_t*)pk;
                kb[nt][1] = *(const uint32_t*)(pk + 8);
            }
            #pragma unroll
            for (int nt = 0; nt < 8; nt++)
                mma_f16(sacc[nt], qa[kc], kb[nt]);
        }

        float mt0 = -INFINITY, mt1 = -INFINITY;
        #pragma unroll
        for (int nt = 0; nt < 8; nt++) {
            mt0 = fmaxf(mt0, fmaxf(sacc[nt][0], sacc[nt][1]));
            mt1 = fmaxf(mt1, fmaxf(sacc[nt][2], sacc[nt][3]));
        }
        mt0 = fmaxf(mt0, __shfl_xor_sync(~0u, mt0, 1));
        mt0 = fmaxf(mt0, __shfl_xor_sync(~0u, mt0, 2));
        mt1 = fmaxf(mt1, __shfl_xor_sync(~0u, mt1, 1));
        mt1 = fmaxf(mt1, __shfl_xor_sync(~0u, mt1, 2));
        float mn0 = fmaxf(m0, mt0), mn1 = fmaxf(m1, mt1);
        float sc0 = expf(m0 - mn0), sc1 = expf(m1 - mn1);
        m0 = mn0; m1 = mn1;

        float ts0 = 0.f, ts1 = 0.f;
        uint32_t ph[8][2];
        #pragma unroll
        for (int nt = 0; nt < 8; nt++) {
            float p0 = expf(sacc[nt][0] - mn0), p1 = expf(sacc[nt][1] - mn0);
            float p2 = expf(sacc[nt][2] - mn1), p3 = expf(sacc[nt][3] - mn1);
            ts0 += p0 + p1; ts1 += p2 + p3;
            __half2 h0 = __floats2half2_rn(p0, p1);
            __half2 h1 = __floats2half2_rn(p2, p3);
            ph[nt][0] = *(uint32_t*)&h0;
            ph[nt][1] = *(uint32_t*)&h1;
        }
        ts0 += __shfl_xor_sync(~0u, ts0, 1); ts0 += __shfl_xor_sync(~0u, ts0, 2);
        ts1 += __shfl_xor_sync(~0u, ts1, 1); ts1 += __shfl_xor_sync(~0u, ts1, 2);
        l0 = l0 * sc0 + ts0;
        l1 = l1 * sc1 + ts1;
        #pragma unroll
        for (int nt = 0; nt < 8; nt++) {
            Oacc[nt][0] *= sc0; Oacc[nt][1] *= sc0;
            Oacc[nt][2] *= sc1; Oacc[nt][3] *= sc1;
        }

        #pragma unroll
        for (int kc = 0; kc < 4; kc++) {
            uint32_t vb[8][2];
            #pragma unroll
            for (int nt = 0; nt < 8; nt++) {
                const __half* pv = Vb + (nt * 8 + (lane >> 2)) * 72 + kc * 16 + ccol;
                vb[nt][0] = *(const uint32_t*)pv;
                vb[nt][1] = *(const uint32_t*)(pv + 8);
            }
            uint32_t af[4] = {ph[2*kc][0], ph[2*kc][1], ph[2*kc+1][0], ph[2*kc+1][1]};
            #pragma unroll
            for (int nt = 0; nt < 8; nt++)
                mma_f16(Oacc[nt], af, vb[nt]);
        }
    }

    const int b = z / H_, h = z % H_;
    float inv0 = SCALE_INV / l0, inv1 = SCALE_INV / l1;
    size_t s0 = (size_t)(b * S_ + q0 + r0) * E_ + h * 64 + ccol;
    size_t s1 = (size_t)(b * S_ + q0 + r0 + 8) * E_ + h * 64 + ccol;
    #pragma unroll
    for (int nt = 0; nt < 8; nt++) {
        *(__half2*)&merged[s0 + nt * 8] =
            __floats2half2_rn(Oacc[nt][0] * inv0, Oacc[nt][1] * inv0);
        *(__half2*)&merged[s1 + nt * 8] =
            __floats2half2_rn(Oacc[nt][2] * inv1, Oacc[nt][3] * inv1);
    }
}

// ---------------- block reductions (R9 LN path) ----------------
__device__ __forceinline__ float block_reduce(float v) {
    __shared__ float sh[8];
    int lane = threadIdx.x & 31, wid = threadIdx.x >> 5;
    #pragma unroll
    for (int o = 16; o; o >>= 1) v += __shfl_xor_sync(0xffffffffu, v, o);
    if (lane == 0) sh[wid] = v;
    __syncthreads();
    if (wid == 0) {
        v = (lane < 8) ? sh[lane] : 0.0f;
        #pragma unroll
        for (int o = 4; o; o >>= 1) v += __shfl_xor_sync(0xffffffffu, v, o);
        if (lane == 0) sh[0] = v;
    }
    __syncthreads();
    float r = sh[0];
    __syncthreads();
    return r;
}

__global__ __launch_bounds__(256) void ln_kernel(
    const float* __restrict__ in, const float* __restrict__ g,
    const float* __restrict__ bb, __half* __restrict__ out)
{
    long long base = (long long)blockIdx.x * E_;
    int t = threadIdx.x;
    float v[3];
    #pragma unroll
    for (int i = 0; i < 3; i++) v[i] = in[base + t + i*256];
    float s  = block_reduce(v[0] + v[1] + v[2]);
    float sq = block_reduce(v[0]*v[0] + v[1]*v[1] + v[2]*v[2]);
    float mean = s * (1.0f/E_);
    float rstd = rsqrtf(sq * (1.0f/E_) - mean*mean + 1e-5f);
    #pragma unroll
    for (int i = 0; i < 3; i++) {
        int c = t + i*256;
        out[base + c] = __float2half_rn((v[i] - mean) * rstd * g[c] + bb[c]);
    }
}

__global__ __launch_bounds__(256) void ln2_ln3_kernel(
    const float* __restrict__ oproj, const float* __restrict__ x,
    const float* __restrict__ g2, const float* __restrict__ b2,
    const float* __restrict__ g3, const float* __restrict__ b3,
    float* __restrict__ r1, __half* __restrict__ f)
{
    long long base = (long long)blockIdx.x * E_;
    int t = threadIdx.x;
    float v[3];
    #pragma unroll
    for (int i = 0; i < 3; i++) v[i] = oproj[base + t + i*256];
    float s  = block_reduce(v[0] + v[1] + v[2]);
    float sq = block_reduce(v[0]*v[0] + v[1]*v[1] + v[2]*v[2]);
    float mean = s * (1.0f/E_);
    float rstd = rsqrtf(sq * (1.0f/E_) - mean*mean + 1e-5f);
    #pragma unroll
    for (int i = 0; i < 3; i++) {
        int c = t + i*256;
        v[i] = (v[i] - mean) * rstd * g2[c] + b2[c] + x[base + c];
        r1[base + c] = v[i];
    }
    float s2  = block_reduce(v[0] + v[1] + v[2]);
    float sq2 = block_reduce(v[0]*v[0] + v[1]*v[1] + v[2]*v[2]);
    float mean2 = s2 * (1.0f/E_);
    float rstd2 = rsqrtf(sq2 * (1.0f/E_) - mean2*mean2 + 1e-5f);
    #pragma unroll
    for (int i = 0; i < 3; i++) {
        int c = t + i*256;
        f[base + c] = __float2half_rn((v[i] - mean2) * rstd2 * g3[c] + b3[c]);
    }
}

__global__ __launch_bounds__(256) void ln4_ln1_kernel(
    const float* __restrict__ f2, const float* __restrict__ r1,
    const float* __restrict__ x,
    const float* __restrict__ g4, const float* __restrict__ b4,
    const float* __restrict__ g1, const float* __restrict__ b1,
    float* __restrict__ xout, __half* __restrict__ hout)
{
    long long base = (long long)blockIdx.x * E_;
    int t = threadIdx.x;
    float v[3];
    #pragma unroll
    for (int i = 0; i < 3; i++) v[i] = f2[base + t + i*256];
    float s  = block_reduce(v[0] + v[1] + v[2]);
    float sq = block_reduce(v[0]*v[0] + v[1]*v[1] + v[2]*v[2]);
    float mean = s * (1.0f/E_);
    float rstd = rsqrtf(sq * (1.0f/E_) - mean*mean + 1e-5f);
    #pragma unroll
    for (int i = 0; i < 3; i++) {
        int c = t + i*256;
        v[i] = (v[i] - mean) * rstd * g4[c] + b4[c] + r1[base + c] + x[base + c];
        xout[base + c] = v[i];
    }
    if (g1 == nullptr) return;
    float s2  = block_reduce(v[0] + v[1] + v[2]);
    float sq2 = block_reduce(v[0]*v[0] + v[1]*v[1] + v[2]*v[2]);
    float mean2 = s2 * (1.0f/E_);
    float rstd2 = rsqrtf(sq2 * (1.0f/E_) - mean2*mean2 + 1e-5f);
    #pragma unroll
    for (int i = 0; i < 3; i++) {
        int c = t + i*256;
        hout[base + c] = __float2half_rn((v[i] - mean2) * rstd2 * g1[c] + b1[c]);
    }
}

// -------- weight transpose + halve: in [L][K][N] f32 -> out [L][N][K] half --
__global__ __launch_bounds__(256) void transpose_h(
    const float* __restrict__ in, __half* __restrict__ out, int K, int N)
{
    __shared__ float t[32][33];
    size_t lofs = (size_t)blockIdx.z * K * N;
    in += lofs; out += lofs;
    int n0 = blockIdx.x * 32, k0 = blockIdx.y * 32;
    int tx = threadIdx.x & 31, ty = threadIdx.x >> 5;   // 32 x 8
    #pragma unroll
    for (int i = 0; i < 4; i++)
        t[ty + i*8][tx] = in[(size_t)(k0 + ty + i*8) * N + n0 + tx];
    __syncthreads();
    #pragma unroll
    for (int i = 0; i < 4; i++)
        out[(size_t)(n0 + ty + i*8) * K + k0 + tx] = __float2half_rn(t[tx][ty + i*8]);
}

// ---------------- host orchestration ----------------
extern "C" void kernel_launch(void* const* d_in, const int* in_sizes, int n_in,
                              void* d_out, int out_size)
{
    (void)in_sizes; (void)n_in; (void)out_size;

    const float* x_in  = (const float*)d_in[0];
    const float* Wqkv  = (const float*)d_in[1];
    const float* bqkv  = (const float*)d_in[2];
    const float* Wp    = (const float*)d_in[3];
    const float* bp    = (const float*)d_in[4];
    const float* W1    = (const float*)d_in[5];
    const float* b1    = (const float*)d_in[6];
    const float* W2    = (const float*)d_in[7];
    const float* b2    = (const float*)d_in[8];
    const float* g1    = (const float*)d_in[9];
    const float* be1   = (const float*)d_in[10];
    const float* g2    = (const float*)d_in[11];
    const float* be2   = (const float*)d_in[12];
    const float* g3    = (const float*)d_in[13];
    const float* be3   = (const float*)d_in[14];
    const float* g4    = (const float*)d_in[15];
    const float* be4   = (const float*)d_in[16];

    static bool attr_done = false;
    if (!attr_done) {
        cudaFuncSetAttribute(gemm_h<0>,
                             cudaFuncAttributeMaxDynamicSharedMemorySize, GH_SMEM);
        cudaFuncSetAttribute(gemm_h<1>,
                             cudaFuncAttributeMaxDynamicSharedMemorySize, GH_SMEM);
        cudaFuncSetAttribute(gemm_h<2>,
                             cudaFuncAttributeMaxDynamicSharedMemorySize, GH_SMEM);
        cudaFuncSetAttribute(gemm_h64,
                             cudaFuncAttributeMaxDynamicSharedMemorySize, G64_SMEM);
        cudaFuncSetAttribute(flash2_kernel,
                             cudaFuncAttributeMaxDynamicSharedMemorySize, FA2_SMEM);
        attr_done = true;
    }

    __half *p_h, *p_q, *p_k, *p_v, *p_merged, *p_f, *p_ff;
    float *p_oproj, *p_r1, *p_f2, *p_x;
    __half *w_qkv, *w_p, *w_1, *w_2;
    cudaGetSymbolAddress((void**)&p_h, g_h);
    cudaGetSymbolAddress((void**)&p_q, g_q);
    cudaGetSymbolAddress((void**)&p_k, g_k);
    cudaGetSymbolAddress((void**)&p_v, g_v);
    cudaGetSymbolAddress((void**)&p_merged, g_merged);
    cudaGetSymbolAddress((void**)&p_oproj, g_oproj);
    cudaGetSymbolAddress((void**)&p_r1, g_r1);
    cudaGetSymbolAddress((void**)&p_f, g_f);
    cudaGetSymbolAddress((void**)&p_ff, g_ff);
    cudaGetSymbolAddress((void**)&p_f2, g_f2);
    cudaGetSymbolAddress((void**)&p_x, g_x);
    cudaGetSymbolAddress((void**)&w_qkv, g_Wqkv_t);
    cudaGetSymbolAddress((void**)&w_p, g_Wp_t);
    cudaGetSymbolAddress((void**)&w_1, g_W1_t);
    cudaGetSymbolAddress((void**)&w_2, g_W2_t);

    // pre-transpose + halve all weights (once per launch)
    transpose_h<<<dim3(E3_/32, E_/32, L_), 256>>>(Wqkv, w_qkv, E_, E3_);
    transpose_h<<<dim3(E_/32,  E_/32, L_), 256>>>(Wp,   w_p,   E_, E_);
    transpose_h<<<dim3(FF_/32, E_/32, L_), 256>>>(W1,   w_1,   E_, FF_);
    transpose_h<<<dim3(E_/32, FF_/32, L_), 256>>>(W2,   w_2,   FF_, E_);

    cudaMemcpyAsync(p_x, x_in, (size_t)NTOK * E_ * sizeof(float),
                    cudaMemcpyDeviceToDevice, 0);

    // h = LN1_0(x)
    ln_kernel<<<NTOK, 256>>>(p_x, g1, be1, p_h);

    for (int l = 0; l < L_; ++l) {
        const __half* Wqkv_l = w_qkv + (size_t)l * E_ * E3_;
        const float*  bqkv_l = bqkv + (size_t)l * E3_;
        const __half* Wp_l   = w_p  + (size_t)l * E_ * E_;
        const float*  bp_l   = bp   + (size_t)l * E_;
        const __half* W1_l   = w_1  + (size_t)l * E_ * FF_;
        const float*  b1_l   = b1   + (size_t)l * FF_;
        const __half* W2_l   = w_2  + (size_t)l * FF_ * E_;
        const float*  b2_l   = b2   + (size_t)l * E_;
        const float* g2_l = g2 + (size_t)l * E_, *be2_l = be2 + (size_t)l * E_;
        const float* g3_l = g3 + (size_t)l * E_, *be3_l = be3 + (size_t)l * E_;
        const float* g4_l = g4 + (size_t)l * E_, *be4_l = be4 + (size_t)l * E_;

        // qkv = h @ Wqkv + bqkv -> split q,k (row-major) + v (transposed), half
        gemm_h<2><<<dim3(E3_/128, NTOK/128), 256, GH_SMEM>>>(
            p_h, Wqkv_l, bqkv_l, nullptr, NTOK, E3_, E_, p_q, p_k, p_v);
        // fused flash attention (online softmax) -> merged (half)
        flash2_kernel<<<dim3(S_/64, BH), 128, FA2_SMEM>>>(p_q, p_k, p_v, p_merged);
        // oproj = merged @ Wp + bp (f32) — BM=64 variant, 192 CTAs
        gemm_h64<<<dim3(E_/128, NTOK/64), 128, G64_SMEM>>>(
            p_merged, Wp_l, bp_l, p_oproj, NTOK, E_, E_);
        // r1 = LN2(oproj) + x ; f = LN3(r1) (half)
        ln2_ln3_kernel<<<NTOK, 256>>>(p_oproj, p_x, g2_l, be2_l, g3_l, be3_l, p_r1, p_f);
        // ff = gelu(f @ W1 + b1) (half)
        gemm_h<1><<<dim3(FF_/128, NTOK/128), 256, GH_SMEM>>>(
            p_f, W1_l, b1_l, p_ff, NTOK, FF_, E_, nullptr, nullptr, nullptr);
        // f2 = ff @ W2 + b2 (f32) — BM=64 variant, 192 CTAs
        gemm_h64<<<dim3(E_/128, NTOK/64), 128, G64_SMEM>>>(
            p_ff, W2_l, b2_l, p_f2, NTOK, E_, FF_);
        // x = LN4(f2) + r1 + x ; h = LN1_{l+1}(x) (half)
        const float* g1n  = (l + 1 < L_) ? g1  + (size_t)(l + 1) * E_ : nullptr;
        const float* be1n = (l + 1 < L_) ? be1 + (size_t)(l + 1) * E_ : nullptr;
        ln4_ln1_kernel<<<NTOK, 256>>>(p_f2, p_r1, p_x, g4_l, be4_l, g1n, be1n, p_x, p_h);
    }

    cudaMemcpyAsync(d_out, p_x, (size_t)NTOK * E_ * sizeof(float),
                    cudaMemcpyDeviceToDevice, 0);
}

// round 15
// speedup vs baseline: 1.1079x; 1.1079x over previous
#include <cuda_runtime.h>
#include <cuda_fp16.h>
#include <math.h>
#include <stdint.h>

#define B_   4
#define S_   512
#define E_   768
#define H_   12
#define D_   64
#define FF_  3072
#define L_   12
#define NTOK (B_*S_)     // 2048
#define BH   (B_*H_)     // 48
#define E3_  (3*E_)      // 2304

#define SCALE_INV 0.03608439182435161f   // 1/sqrt(768), applied AFTER softmax

// ---------------- scratch (static __device__, no allocation) ----------------
__device__ __half g_h[NTOK*E_];
__device__ __half g_q[BH*S_*D_];        // [z][s][d]
__device__ __half g_k[BH*S_*D_];        // [z][s][d]
__device__ __half g_v[BH*D_*S_];        // [z][d][s]  (transposed for PV)
__device__ __half g_merged[NTOK*E_];
__device__ float  g_oproj[NTOK*E_];
__device__ float  g_r1[NTOK*E_];
__device__ __half g_f[NTOK*E_];
__device__ __half g_ff[NTOK*FF_];
__device__ float  g_f2[NTOK*E_];
__device__ float  g_x[NTOK*E_];
// fp16 + transposed weight copies ([N][K] K-major per layer)
__device__ __half g_Wqkv_t[(size_t)L_*E_*E3_];   // qkv: column-permuted (q|k|v)
__device__ float  g_bqkv_p[(size_t)L_*E3_];      // permuted bias
__device__ __half g_Wp_t[(size_t)L_*E_*E_];
__device__ __half g_W1_t[(size_t)L_*E_*FF_];
__device__ __half g_W2_t[(size_t)L_*FF_*E_];

// ---------------- helpers ----------------
__device__ __forceinline__ void mma_f16(float* c, const uint32_t* a, const uint32_t* b) {
    asm volatile(
        "mma.sync.aligned.m16n8k16.row.col.f32.f16.f16.f32 "
        "{%0,%1,%2,%3}, {%4,%5,%6,%7}, {%8,%9}, {%0,%1,%2,%3};"
        : "+f"(c[0]), "+f"(c[1]), "+f"(c[2]), "+f"(c[3])
        : "r"(a[0]), "r"(a[1]), "r"(a[2]), "r"(a[3]), "r"(b[0]), "r"(b[1]));
}

__device__ __forceinline__ void cp_async16(void* smem, const void* gmem) {
    uint32_t s = (uint32_t)__cvta_generic_to_shared(smem);
    asm volatile("cp.async.cg.shared.global [%0], [%1], 16;\n" :: "r"(s), "l"(gmem));
}
__device__ __forceinline__ void cp_commit() {
    asm volatile("cp.async.commit_group;\n");
}
template<int N> __device__ __forceinline__ void cp_wait() {
    asm volatile("cp.async.wait_group %0;\n" :: "n"(N));
}

__device__ __forceinline__ float gelu_exact(float x) {
    return 0.5f * x * (1.0f + erff(x * 0.7071067811865476f));
}

// ---------------- fp16 tensor-core GEMM, cp.async 3-stage, BK=64 ------------
// C = A[M,K](half) @ Bt[N,K](half, pre-transposed) + bias(f32).
// ACT: 0 plain f32 out; 1 gelu -> half out; 2 qkv-split (PERMUTED weights:
//      region = bn/768 selects q/k/v; q,k coalesced half2; v transposed).
#define GH_STAGE 36864                       // 18432 A + 18432 B
#define GH_SMEM  (3 * GH_STAGE)              // 110592

template<int ACT>
__global__ void __launch_bounds__(256, 2) gemm_h(
    const __half* __restrict__ A, const __half* __restrict__ Bt,
    const float* __restrict__ bias, void* __restrict__ Cout,
    int M, int N, int K,
    __half* __restrict__ qp, __half* __restrict__ kp, __half* __restrict__ vp)
{
    extern __shared__ char smem[];
    const int tid  = threadIdx.x;
    const int lane = tid & 31;
    const int warp = tid >> 5;
    const int wm = (warp & 1) * 64;           // WRM=2
    const int wn = (warp >> 1) * 32;          // WRN=4
    const int bm = blockIdx.y * 128;
    const int bn = blockIdx.x * 128;
    const int niter = K / 64;

    float acc[4][4][4] = {};

    auto issue = [&](int s) {
        char* st = smem + (s % 3) * GH_STAGE;
        int k0 = s * 64;
        #pragma unroll
        for (int r = 0; r < 4; r++) {
            int ch = tid + r * 256;
            int row = ch >> 3, kq = ch & 7;
            cp_async16(st + row * 144 + kq * 16,
                       &A[(size_t)(bm + row) * K + k0 + kq * 8]);
            cp_async16(st + 18432 + row * 144 + kq * 16,
                       &Bt[(size_t)(bn + row) * K + k0 + kq * 8]);
        }
    };

    auto compute = [&](int buf) {
        const uint32_t* Ab = (const uint32_t*)(smem + buf * GH_STAGE);
        const uint32_t* Bb = (const uint32_t*)(smem + buf * GH_STAGE + 18432);
        #pragma unroll
        for (int kk = 0; kk < 4; kk++) {            // four k16 slices per BK=64
            int c0 = kk * 8 + (lane & 3);
            uint32_t af[4][4];
            #pragma unroll
            for (int i = 0; i < 4; i++) {
                const uint32_t* p = &Ab[(wm + i * 16 + (lane >> 2)) * 36 + c0];
                af[i][0] = p[0];
                af[i][1] = p[288];      // +8 rows * 36 words
                af[i][2] = p[4];        // +8 halves
                af[i][3] = p[292];
            }
            uint32_t bf[4][2];
            #pragma unroll
            for (int j = 0; j < 4; j++) {
                const uint32_t* p = &Bb[(wn + j * 8 + (lane >> 2)) * 36 + c0];
                bf[j][0] = p[0];
                bf[j][1] = p[4];        // k+8
            }
            #pragma unroll
            for (int i = 0; i < 4; i++)
                #pragma unroll
                for (int j = 0; j < 4; j++)
                    mma_f16(acc[i][j], af[i], bf[j]);
        }
    };

    #pragma unroll
    for (int s = 0; s < 2; s++) { if (s < niter) issue(s); cp_commit(); }
    for (int it = 0; it < niter; ++it) {
        cp_wait<1>();
        __syncthreads();
        if (it + 2 < niter) issue(it + 2);
        cp_commit();
        compute(it % 3);
    }

    // ---- epilogue ----
    const int region = (ACT == 2) ? (bn / E_) : 0;   // 0=q 1=k 2=v (tile never straddles)
    const int hd0    = (ACT == 2) ? (bn % E_) : 0;
    #pragma unroll
    for (int i = 0; i < 4; i++) {
        #pragma unroll
        for (int j = 0; j < 4; j++) {
            int row = bm + wm + i * 16 + (lane >> 2);
            int col = bn + wn + j * 8 + (lane & 3) * 2;
            float2 bv = make_float2(0.f, 0.f);
            if (bias) bv = *(const float2*)&bias[col];
            float o[2][2] = {{acc[i][j][0] + bv.x, acc[i][j][1] + bv.y},
                             {acc[i][j][2] + bv.x, acc[i][j][3] + bv.y}};
            if (ACT == 0) {
                float* C = (float*)Cout;
                *(float2*)&C[(size_t)row * N + col]       = make_float2(o[0][0], o[0][1]);
                *(float2*)&C[(size_t)(row + 8) * N + col] = make_float2(o[1][0], o[1][1]);
            } else if (ACT == 1) {
                __half* C = (__half*)Cout;
                *(__half2*)&C[(size_t)row * N + col] =
                    __floats2half2_rn(gelu_exact(o[0][0]), gelu_exact(o[0][1]));
                *(__half2*)&C[(size_t)(row + 8) * N + col] =
                    __floats2half2_rn(gelu_exact(o[1][0]), gelu_exact(o[1][1]));
            } else {
                // permuted qkv: local col within region
                int hd = hd0 + wn + j * 8 + (lane & 3) * 2;
                int h = hd >> 6, d = hd & 63;
                #pragma unroll
                for (int r = 0; r < 2; r++) {
                    int rr = row + r * 8;
                    int b = rr >> 9, s = rr & 511;
                    int z = b * H_ + h;
                    __half2 val = __floats2half2_rn(o[r][0], o[r][1]);
                    if (region == 0) {
                        *(__half2*)&qp[((size_t)z * S_ + s) * D_ + d] = val;
                    } else if (region == 1) {
                        *(__half2*)&kp[((size_t)z * S_ + s) * D_ + d] = val;
                    } else {
                        vp[((size_t)z * D_ + d)     * S_ + s] = __low2half(val);
                        vp[((size_t)z * D_ + d + 1) * S_ + s] = __high2half(val);
                    }
                }
            }
        }
    }
}

// ---------------- flash attention v2 (R12: 64 q-rows, 128 threads) ----------
#define FA2_SMEM 64512     // Q 9216 + 3*K 27648 + 3*V 27648 bytes

__global__ void __launch_bounds__(128, 2) flash2_kernel(
    const __half* __restrict__ q, const __half* __restrict__ k,
    const __half* __restrict__ vt, __half* __restrict__ merged)
{
    extern __shared__ __half hs[];
    __half* Qs = hs;                     // 64 x 72
    __half* Ks = hs + 4608;              // 3 x (64 x 72)
    __half* Vs = hs + 4 * 4608;          // 3 x (64 x 72)

    const int tid = threadIdx.x, lane = tid & 31, warp = tid >> 5;
    const int z = blockIdx.y, q0 = blockIdx.x * 64;
    const __half* qg = q  + (size_t)z * S_ * D_ + (size_t)q0 * D_;
    const __half* kg = k  + (size_t)z * S_ * D_;
    const __half* vg = vt + (size_t)z * D_ * S_;

    auto loadKV = [&](int t) {
        __half* dk = Ks + (t % 3) * 4608;
        __half* dv = Vs + (t % 3) * 4608;
        const __half* sk = kg + (size_t)t * 64 * 64;
        #pragma unroll
        for (int r = 0; r < 4; r++) {
            int ch = tid + r * 128;
            int row = ch >> 3, c = ch & 7;
            cp_async16(dk + row * 72 + c * 8, sk + row * 64 + c * 8);
            cp_async16(dv + row * 72 + c * 8, vg + row * 512 + t * 64 + c * 8);
        }
    };

    #pragma unroll
    for (int r = 0; r < 4; r++) {
        int ch = tid + r * 128;
        int row = ch >> 3, c = ch & 7;
        cp_async16(Qs + row * 72 + c * 8, qg + row * 64 + c * 8);
    }
    loadKV(0); cp_commit();
    loadKV(1); cp_commit();

    uint32_t qa[4][4];
    float Oacc[8][4] = {};
    float m0 = -INFINITY, m1 = -INFINITY, l0 = 0.f, l1 = 0.f;

    const int r0 = warp * 16 + (lane >> 2);
    const int ccol = (lane & 3) * 2;

    for (int t = 0; t < 8; t++) {
        cp_wait<1>();
        __syncthreads();
        if (t == 0) {
            #pragma unroll
            for (int kc = 0; kc < 4; kc++) {
                qa[kc][0] = *(const uint32_t*)(Qs + r0 * 72 + kc * 16 + ccol);
                qa[kc][1] = *(const uint32_t*)(Qs + (r0 + 8) * 72 + kc * 16 + ccol);
                qa[kc][2] = *(const uint32_t*)(Qs + r0 * 72 + kc * 16 + 8 + ccol);
                qa[kc][3] = *(const uint32_t*)(Qs + (r0 + 8) * 72 + kc * 16 + 8 + ccol);
            }
        }
        if (t + 2 < 8) loadKV(t + 2);
        cp_commit();

        const __half* Kt = Ks + (t % 3) * 4608;
        const __half* Vb = Vs + (t % 3) * 4608;

        float sacc[8][4] = {};
        #pragma unroll
        for (int kc = 0; kc < 4; kc++) {
            uint32_t kb[8][2];
            #pragma unroll
            for (int nt = 0; nt < 8; nt++) {
                const __half* pk = Kt + (nt * 8 + (lane >> 2)) * 72 + kc * 16 + ccol;
                kb[nt][0] = *(const uint32_t*)pk;
                kb[nt][1] = *(const uint32_t*)(pk + 8);
            }
            #pragma unroll
            for (int nt = 0; nt < 8; nt++)
                mma_f16(sacc[nt], qa[kc], kb[nt]);
        }

        float mt0 = -INFINITY, mt1 = -INFINITY;
        #pragma unroll
        for (int nt = 0; nt < 8; nt++) {
            mt0 = fmaxf(mt0, fmaxf(sacc[nt][0], sacc[nt][1]));
            mt1 = fmaxf(mt1, fmaxf(sacc[nt][2], sacc[nt][3]));
        }
        mt0 = fmaxf(mt0, __shfl_xor_sync(~0u, mt0, 1));
        mt0 = fmaxf(mt0, __shfl_xor_sync(~0u, mt0, 2));
        mt1 = fmaxf(mt1, __shfl_xor_sync(~0u, mt1, 1));
        mt1 = fmaxf(mt1, __shfl_xor_sync(~0u, mt1, 2));
        float mn0 = fmaxf(m0, mt0), mn1 = fmaxf(m1, mt1);
        float sc0 = expf(m0 - mn0), sc1 = expf(m1 - mn1);
        m0 = mn0; m1 = mn1;

        float ts0 = 0.f, ts1 = 0.f;
        uint32_t ph[8][2];
        #pragma unroll
        for (int nt = 0; nt < 8; nt++) {
            float p0 = expf(sacc[nt][0] - mn0), p1 = expf(sacc[nt][1] - mn0);
            float p2 = expf(sacc[nt][2] - mn1), p3 = expf(sacc[nt][3] - mn1);
            ts0 += p0 + p1; ts1 += p2 + p3;
            __half2 h0 = __floats2half2_rn(p0, p1);
            __half2 h1 = __floats2half2_rn(p2, p3);
            ph[nt][0] = *(uint32_t*)&h0;
            ph[nt][1] = *(uint32_t*)&h1;
        }
        ts0 += __shfl_xor_sync(~0u, ts0, 1); ts0 += __shfl_xor_sync(~0u, ts0, 2);
        ts1 += __shfl_xor_sync(~0u, ts1, 1); ts1 += __shfl_xor_sync(~0u, ts1, 2);
        l0 = l0 * sc0 + ts0;
        l1 = l1 * sc1 + ts1;
        #pragma unroll
        for (int nt = 0; nt < 8; nt++) {
            Oacc[nt][0] *= sc0; Oacc[nt][1] *= sc0;
            Oacc[nt][2] *= sc1; Oacc[nt][3] *= sc1;
        }

        #pragma unroll
        for (int kc = 0; kc < 4; kc++) {
            uint32_t vb[8][2];
            #pragma unroll
            for (int nt = 0; nt < 8; nt++) {
                const __half* pv = Vb + (nt * 8 + (lane >> 2)) * 72 + kc * 16 + ccol;
                vb[nt][0] = *(const uint32_t*)pv;
                vb[nt][1] = *(const uint32_t*)(pv + 8);
            }
            uint32_t af[4] = {ph[2*kc][0], ph[2*kc][1], ph[2*kc+1][0], ph[2*kc+1][1]};
            #pragma unroll
            for (int nt = 0; nt < 8; nt++)
                mma_f16(Oacc[nt], af, vb[nt]);
        }
    }

    const int b = z / H_, h = z % H_;
    float inv0 = SCALE_INV / l0, inv1 = SCALE_INV / l1;
    size_t s0 = (size_t)(b * S_ + q0 + r0) * E_ + h * 64 + ccol;
    size_t s1 = (size_t)(b * S_ + q0 + r0 + 8) * E_ + h * 64 + ccol;
    #pragma unroll
    for (int nt = 0; nt < 8; nt++) {
        *(__half2*)&merged[s0 + nt * 8] =
            __floats2half2_rn(Oacc[nt][0] * inv0, Oacc[nt][1] * inv0);
        *(__half2*)&merged[s1 + nt * 8] =
            __floats2half2_rn(Oacc[nt][2] * inv1, Oacc[nt][3] * inv1);
    }
}

// ---------------- block reductions (R9 LN path) ----------------
__device__ __forceinline__ float block_reduce(float v) {
    __shared__ float sh[8];
    int lane = threadIdx.x & 31, wid = threadIdx.x >> 5;
    #pragma unroll
    for (int o = 16; o; o >>= 1) v += __shfl_xor_sync(0xffffffffu, v, o);
    if (lane == 0) sh[wid] = v;
    __syncthreads();
    if (wid == 0) {
        v = (lane < 8) ? sh[lane] : 0.0f;
        #pragma unroll
        for (int o = 4; o; o >>= 1) v += __shfl_xor_sync(0xffffffffu, v, o);
        if (lane == 0) sh[0] = v;
    }
    __syncthreads();
    float r = sh[0];
    __syncthreads();
    return r;
}

__global__ __launch_bounds__(256) void ln_kernel(
    const float* __restrict__ in, const float* __restrict__ g,
    const float* __restrict__ bb, __half* __restrict__ out)
{
    long long base = (long long)blockIdx.x * E_;
    int t = threadIdx.x;
    float v[3];
    #pragma unroll
    for (int i = 0; i < 3; i++) v[i] = in[base + t + i*256];
    float s  = block_reduce(v[0] + v[1] + v[2]);
    float sq = block_reduce(v[0]*v[0] + v[1]*v[1] + v[2]*v[2]);
    float mean = s * (1.0f/E_);
    float rstd = rsqrtf(sq * (1.0f/E_) - mean*mean + 1e-5f);
    #pragma unroll
    for (int i = 0; i < 3; i++) {
        int c = t + i*256;
        out[base + c] = __float2half_rn((v[i] - mean) * rstd * g[c] + bb[c]);
    }
}

__global__ __launch_bounds__(256) void ln2_ln3_kernel(
    const float* __restrict__ oproj, const float* __restrict__ x,
    const float* __restrict__ g2, const float* __restrict__ b2,
    const float* __restrict__ g3, const float* __restrict__ b3,
    float* __restrict__ r1, __half* __restrict__ f)
{
    long long base = (long long)blockIdx.x * E_;
    int t = threadIdx.x;
    float v[3];
    #pragma unroll
    for (int i = 0; i < 3; i++) v[i] = oproj[base + t + i*256];
    float s  = block_reduce(v[0] + v[1] + v[2]);
    float sq = block_reduce(v[0]*v[0] + v[1]*v[1] + v[2]*v[2]);
    float mean = s * (1.0f/E_);
    float rstd = rsqrtf(sq * (1.0f/E_) - mean*mean + 1e-5f);
    #pragma unroll
    for (int i = 0; i < 3; i++) {
        int c = t + i*256;
        v[i] = (v[i] - mean) * rstd * g2[c] + b2[c] + x[base + c];
        r1[base + c] = v[i];
    }
    float s2  = block_reduce(v[0] + v[1] + v[2]);
    float sq2 = block_reduce(v[0]*v[0] + v[1]*v[1] + v[2]*v[2]);
    float mean2 = s2 * (1.0f/E_);
    float rstd2 = rsqrtf(sq2 * (1.0f/E_) - mean2*mean2 + 1e-5f);
    #pragma unroll
    for (int i = 0; i < 3; i++) {
        int c = t + i*256;
        f[base + c] = __float2half_rn((v[i] - mean2) * rstd2 * g3[c] + b3[c]);
    }
}

__global__ __launch_bounds__(256) void ln4_ln1_kernel(
    const float* __restrict__ f2, const float* __restrict__ r1,
    const float* __restrict__ x,
    const float* __restrict__ g4, const float* __restrict__ b4,
    const float* __restrict__ g1, const float* __restrict__ b1,
    float* __restrict__ xout, __half* __restrict__ hout)
{
    long long base = (long long)blockIdx.x * E_;
    int t = threadIdx.x;
    float v[3];
    #pragma unroll
    for (int i = 0; i < 3; i++) v[i] = f2[base + t + i*256];
    float s  = block_reduce(v[0] + v[1] + v[2]);
    float sq = block_reduce(v[0]*v[0] + v[1]*v[1] + v[2]*v[2]);
    float mean = s * (1.0f/E_);
    float rstd = rsqrtf(sq * (1.0f/E_) - mean*mean + 1e-5f);
    #pragma unroll
    for (int i = 0; i < 3; i++) {
        int c = t + i*256;
        v[i] = (v[i] - mean) * rstd * g4[c] + b4[c] + r1[base + c] + x[base + c];
        xout[base + c] = v[i];
    }
    if (g1 == nullptr) return;
    float s2  = block_reduce(v[0] + v[1] + v[2]);
    float sq2 = block_reduce(v[0]*v[0] + v[1]*v[1] + v[2]*v[2]);
    float mean2 = s2 * (1.0f/E_);
    float rstd2 = rsqrtf(sq2 * (1.0f/E_) - mean2*mean2 + 1e-5f);
    #pragma unroll
    for (int i = 0; i < 3; i++) {
        int c = t + i*256;
        hout[base + c] = __float2half_rn((v[i] - mean2) * rstd2 * g1[c] + b1[c]);
    }
}

// -------- weight transpose + halve: in [L][K][N] f32 -> out [L][N][K] half --
__global__ __launch_bounds__(256) void transpose_h(
    const float* __restrict__ in, __half* __restrict__ out, int K, int N)
{
    __shared__ float t[32][33];
    size_t lofs = (size_t)blockIdx.z * K * N;
    in += lofs; out += lofs;
    int n0 = blockIdx.x * 32, k0 = blockIdx.y * 32;
    int tx = threadIdx.x & 31, ty = threadIdx.x >> 5;   // 32 x 8
    #pragma unroll
    for (int i = 0; i < 4; i++)
        t[ty + i*8][tx] = in[(size_t)(k0 + ty + i*8) * N + n0 + tx];
    __syncthreads();
    #pragma unroll
    for (int i = 0; i < 4; i++)
        out[(size_t)(n0 + ty + i*8) * K + k0 + tx] = __float2half_rn(t[tx][ty + i*8]);
}

// -------- qkv weight transpose with column permutation ----------------------
// out[n_new][k] = in[k][n_orig], n_orig = (n_new % 768)*3 + n_new/768.
__global__ __launch_bounds__(256) void transpose_qkv(
    const float* __restrict__ in, __half* __restrict__ out)
{
    __shared__ float t[32][33];
    size_t lofs = (size_t)blockIdx.z * E_ * E3_;
    in += lofs; out += lofs;
    int n0 = blockIdx.x * 32, k0 = blockIdx.y * 32;   // n0 within [0,2304)
    int tx = threadIdx.x & 31, ty = threadIdx.x >> 5;
    int c_reg = n0 / E_;                               // 32-tile never straddles
    #pragma unroll
    for (int i = 0; i < 4; i++) {
        int nn = n0 + tx;
        int n_orig = (nn % E_) * 3 + c_reg;
        t[ty + i*8][tx] = in[(size_t)(k0 + ty + i*8) * E3_ + n_orig];
    }
    __syncthreads();
    #pragma unroll
    for (int i = 0; i < 4; i++)
        out[(size_t)(n0 + ty + i*8) * E_ + k0 + tx] = __float2half_rn(t[tx][ty + i*8]);
}

// -------- qkv bias permutation ----------------------------------------------
__global__ __launch_bounds__(256) void permute_bias(
    const float* __restrict__ in, float* __restrict__ out)
{
    int i = blockIdx.x * 256 + threadIdx.x;            // over L*2304
    int l = i / E3_, n = i % E3_;
    int n_orig = (n % E_) * 3 + n / E_;
    out[i] = in[l * E3_ + n_orig];
}

// ---------------- host orchestration ----------------
extern "C" void kernel_launch(void* const* d_in, const int* in_sizes, int n_in,
                              void* d_out, int out_size)
{
    (void)in_sizes; (void)n_in; (void)out_size;

    const float* x_in  = (const float*)d_in[0];
    const float* Wqkv  = (const float*)d_in[1];
    const float* bqkv  = (const float*)d_in[2];
    const float* Wp    = (const float*)d_in[3];
    const float* bp    = (const float*)d_in[4];
    const float* W1    = (const float*)d_in[5];
    const float* b1    = (const float*)d_in[6];
    const float* W2    = (const float*)d_in[7];
    const float* b2    = (const float*)d_in[8];
    const float* g1    = (const float*)d_in[9];
    const float* be1   = (const float*)d_in[10];
    const float* g2    = (const float*)d_in[11];
    const float* be2   = (const float*)d_in[12];
    const float* g3    = (const float*)d_in[13];
    const float* be3   = (const float*)d_in[14];
    const float* g4    = (const float*)d_in[15];
    const float* be4   = (const float*)d_in[16];

    static bool attr_done = false;
    if (!attr_done) {
        cudaFuncSetAttribute(gemm_h<0>,
                             cudaFuncAttributeMaxDynamicSharedMemorySize, GH_SMEM);
        cudaFuncSetAttribute(gemm_h<1>,
                             cudaFuncAttributeMaxDynamicSharedMemorySize, GH_SMEM);
        cudaFuncSetAttribute(gemm_h<2>,
                             cudaFuncAttributeMaxDynamicSharedMemorySize, GH_SMEM);
        cudaFuncSetAttribute(flash2_kernel,
                             cudaFuncAttributeMaxDynamicSharedMemorySize, FA2_SMEM);
        attr_done = true;
    }

    __half *p_h, *p_q, *p_k, *p_v, *p_merged, *p_f, *p_ff;
    float *p_oproj, *p_r1, *p_f2, *p_x, *p_bqkv;
    __half *w_qkv, *w_p, *w_1, *w_2;
    cudaGetSymbolAddress((void**)&p_h, g_h);
    cudaGetSymbolAddress((void**)&p_q, g_q);
    cudaGetSymbolAddress((void**)&p_k, g_k);
    cudaGetSymbolAddress((void**)&p_v, g_v);
    cudaGetSymbolAddress((void**)&p_merged, g_merged);
    cudaGetSymbolAddress((void**)&p_oproj, g_oproj);
    cudaGetSymbolAddress((void**)&p_r1, g_r1);
    cudaGetSymbolAddress((void**)&p_f, g_f);
    cudaGetSymbolAddress((void**)&p_ff, g_ff);
    cudaGetSymbolAddress((void**)&p_f2, g_f2);
    cudaGetSymbolAddress((void**)&p_x, g_x);
    cudaGetSymbolAddress((void**)&p_bqkv, g_bqkv_p);
    cudaGetSymbolAddress((void**)&w_qkv, g_Wqkv_t);
    cudaGetSymbolAddress((void**)&w_p, g_Wp_t);
    cudaGetSymbolAddress((void**)&w_1, g_W1_t);
    cudaGetSymbolAddress((void**)&w_2, g_W2_t);

    // pre-transpose + halve all weights (once per launch)
    transpose_qkv<<<dim3(E3_/32, E_/32, L_), 256>>>(Wqkv, w_qkv);
    permute_bias<<<(L_*E3_)/256, 256>>>(bqkv, p_bqkv);
    transpose_h<<<dim3(E_/32,  E_/32, L_), 256>>>(Wp,   w_p,   E_, E_);
    transpose_h<<<dim3(FF_/32, E_/32, L_), 256>>>(W1,   w_1,   E_, FF_);
    transpose_h<<<dim3(E_/32, FF_/32, L_), 256>>>(W2,   w_2,   FF_, E_);

    cudaMemcpyAsync(p_x, x_in, (size_t)NTOK * E_ * sizeof(float),
                    cudaMemcpyDeviceToDevice, 0);

    // h = LN1_0(x)
    ln_kernel<<<NTOK, 256>>>(p_x, g1, be1, p_h);

    for (int l = 0; l < L_; ++l) {
        const __half* Wqkv_l = w_qkv + (size_t)l * E_ * E3_;
        const float*  bqkv_l = p_bqkv + (size_t)l * E3_;
        const __half* Wp_l   = w_p  + (size_t)l * E_ * E_;
        const float*  bp_l   = bp   + (size_t)l * E_;
        const __half* W1_l   = w_1  + (size_t)l * E_ * FF_;
        const float*  b1_l   = b1   + (size_t)l * FF_;
        const __half* W2_l   = w_2  + (size_t)l * FF_ * E_;
        const float*  b2_l   = b2   + (size_t)l * E_;
        const float* g2_l = g2 + (size_t)l * E_, *be2_l = be2 + (size_t)l * E_;
        const float* g3_l = g3 + (size_t)l * E_, *be3_l = be3 + (size_t)l * E_;
        const float* g4_l = g4 + (size_t)l * E_, *be4_l = be4 + (size_t)l * E_;

        // qkv = h @ Wqkv_perm + bqkv_perm -> q | k | v regions (half)
        gemm_h<2><<<dim3(E3_/128, NTOK/128), 256, GH_SMEM>>>(
            p_h, Wqkv_l, bqkv_l, nullptr, NTOK, E3_, E_, p_q, p_k, p_v);
        // fused flash attention (online softmax) -> merged (half)
        flash2_kernel<<<dim3(S_/64, BH), 128, FA2_SMEM>>>(p_q, p_k, p_v, p_merged);
        // oproj = merged @ Wp + bp (f32)
        gemm_h<0><<<dim3(E_/128, NTOK/128), 256, GH_SMEM>>>(
            p_merged, Wp_l, bp_l, p_oproj, NTOK, E_, E_, nullptr, nullptr, nullptr);
        // r1 = LN2(oproj) + x ; f = LN3(r1) (half)
        ln2_ln3_kernel<<<NTOK, 256>>>(p_oproj, p_x, g2_l, be2_l, g3_l, be3_l, p_r1, p_f);
        // ff = gelu(f @ W1 + b1) (half)
        gemm_h<1><<<dim3(FF_/128, NTOK/128), 256, GH_SMEM>>>(
            p_f, W1_l, b1_l, p_ff, NTOK, FF_, E_, nullptr, nullptr, nullptr);
        // f2 = ff @ W2 + b2 (f32)
        gemm_h<0><<<dim3(E_/128, NTOK/128), 256, GH_SMEM>>>(
            p_ff, W2_l, b2_l, p_f2, NTOK, E_, FF_, nullptr, nullptr, nullptr);
        // x = LN4(f2) + r1 + x ; h = LN1_{l+1}(x) (half)
        const float* g1n  = (l + 1 < L_) ? g1  + (size_t)(l + 1) * E_ : nullptr;
        const float* be1n = (l + 1 < L_) ? be1 + (size_t)(l + 1) * E_ : nullptr;
        ln4_ln1_kernel<<<NTOK, 256>>>(p_f2, p_r1, p_x, g4_l, be4_l, g1n, be1n, p_x, p_h);
    }

    cudaMemcpyAsync(d_out, p_x, (size_t)NTOK * E_ * sizeof(float),
                    cudaMemcpyDeviceToDevice, 0);
}

// round 16
// speedup vs baseline: 1.1443x; 1.0329x over previous
#include <cuda_runtime.h>
#include <cuda_fp16.h>
#include <math.h>
#include <stdint.h>

#define B_   4
#define S_   512
#define E_   768
#define H_   12
#define D_   64
#define FF_  3072
#define L_   12
#define NTOK (B_*S_)     // 2048
#define BH   (B_*H_)     // 48
#define E3_  (3*E_)      // 2304

#define SCALE_INV 0.03608439182435161f   // 1/sqrt(768), applied AFTER softmax

// ---------------- scratch (static __device__, no allocation) ----------------
__device__ __half g_h[NTOK*E_];
__device__ __half g_q[BH*S_*D_];        // [z][s][d]
__device__ __half g_k[BH*S_*D_];        // [z][s][d]
__device__ __half g_v[BH*D_*S_];        // [z][d][s]  (transposed for PV)
__device__ __half g_merged[NTOK*E_];
__device__ float  g_oproj[2*NTOK*E_];   // split-K partials
__device__ float  g_r1[NTOK*E_];
__device__ __half g_f[NTOK*E_];
__device__ __half g_ff[NTOK*FF_];
__device__ float  g_f2[2*NTOK*E_];      // split-K partials
__device__ float  g_x[NTOK*E_];
// fp16 + transposed weight copies ([N][K] K-major per layer)
__device__ __half g_Wqkv_t[(size_t)L_*E_*E3_];   // qkv: column-permuted (q|k|v)
__device__ float  g_bqkv_p[(size_t)L_*E3_];      // permuted bias
__device__ __half g_Wp_t[(size_t)L_*E_*E_];
__device__ __half g_W1_t[(size_t)L_*E_*FF_];
__device__ __half g_W2_t[(size_t)L_*FF_*E_];

// ---------------- helpers ----------------
__device__ __forceinline__ void mma_f16(float* c, const uint32_t* a, const uint32_t* b) {
    asm volatile(
        "mma.sync.aligned.m16n8k16.row.col.f32.f16.f16.f32 "
        "{%0,%1,%2,%3}, {%4,%5,%6,%7}, {%8,%9}, {%0,%1,%2,%3};"
        : "+f"(c[0]), "+f"(c[1]), "+f"(c[2]), "+f"(c[3])
        : "r"(a[0]), "r"(a[1]), "r"(a[2]), "r"(a[3]), "r"(b[0]), "r"(b[1]));
}

__device__ __forceinline__ void cp_async16(void* smem, const void* gmem) {
    uint32_t s = (uint32_t)__cvta_generic_to_shared(smem);
    asm volatile("cp.async.cg.shared.global [%0], [%1], 16;\n" :: "r"(s), "l"(gmem));
}
__device__ __forceinline__ void cp_commit() {
    asm volatile("cp.async.commit_group;\n");
}
template<int N> __device__ __forceinline__ void cp_wait() {
    asm volatile("cp.async.wait_group %0;\n" :: "n"(N));
}

__device__ __forceinline__ float gelu_exact(float x) {
    return 0.5f * x * (1.0f + erff(x * 0.7071067811865476f));
}

// ---------------- fp16 tensor-core GEMM, cp.async 3-stage, BK=64 ------------
// C = A[M,Kfull](half) @ Bt[N,Kfull](half) + bias(f32), over K slice
// [blockIdx.z*Ksub, (blockIdx.z+1)*Ksub). ACT==0 writes partial to
// C + blockIdx.z*M*N, bias only from z==0.
// ACT: 0 plain f32 out (split-K capable); 1 gelu -> half; 2 qkv-split (perm).
#define GH_STAGE 36864                       // 18432 A + 18432 B
#define GH_SMEM  (3 * GH_STAGE)              // 110592

template<int ACT>
__global__ void __launch_bounds__(256, 2) gemm_h(
    const __half* __restrict__ A, const __half* __restrict__ Bt,
    const float* __restrict__ bias, void* __restrict__ Cout,
    int M, int N, int Ksub, int Kfull,
    __half* __restrict__ qp, __half* __restrict__ kp, __half* __restrict__ vp)
{
    extern __shared__ char smem[];
    const int tid  = threadIdx.x;
    const int lane = tid & 31;
    const int warp = tid >> 5;
    const int wm = (warp & 1) * 64;           // WRM=2
    const int wn = (warp >> 1) * 32;          // WRN=4
    const int bm = blockIdx.y * 128;
    const int bn = blockIdx.x * 128;
    const int koff = blockIdx.z * Ksub;
    const int niter = Ksub / 64;

    float acc[4][4][4] = {};

    auto issue = [&](int s) {
        char* st = smem + (s % 3) * GH_STAGE;
        int k0 = koff + s * 64;
        #pragma unroll
        for (int r = 0; r < 4; r++) {
            int ch = tid + r * 256;
            int row = ch >> 3, kq = ch & 7;
            cp_async16(st + row * 144 + kq * 16,
                       &A[(size_t)(bm + row) * Kfull + k0 + kq * 8]);
            cp_async16(st + 18432 + row * 144 + kq * 16,
                       &Bt[(size_t)(bn + row) * Kfull + k0 + kq * 8]);
        }
    };

    auto compute = [&](int buf) {
        const uint32_t* Ab = (const uint32_t*)(smem + buf * GH_STAGE);
        const uint32_t* Bb = (const uint32_t*)(smem + buf * GH_STAGE + 18432);
        #pragma unroll
        for (int kk = 0; kk < 4; kk++) {            // four k16 slices per BK=64
            int c0 = kk * 8 + (lane & 3);
            uint32_t af[4][4];
            #pragma unroll
            for (int i = 0; i < 4; i++) {
                const uint32_t* p = &Ab[(wm + i * 16 + (lane >> 2)) * 36 + c0];
                af[i][0] = p[0];
                af[i][1] = p[288];      // +8 rows * 36 words
                af[i][2] = p[4];        // +8 halves
                af[i][3] = p[292];
            }
            uint32_t bf[4][2];
            #pragma unroll
            for (int j = 0; j < 4; j++) {
                const uint32_t* p = &Bb[(wn + j * 8 + (lane >> 2)) * 36 + c0];
                bf[j][0] = p[0];
                bf[j][1] = p[4];        // k+8
            }
            #pragma unroll
            for (int i = 0; i < 4; i++)
                #pragma unroll
                for (int j = 0; j < 4; j++)
                    mma_f16(acc[i][j], af[i], bf[j]);
        }
    };

    #pragma unroll
    for (int s = 0; s < 2; s++) { if (s < niter) issue(s); cp_commit(); }
    for (int it = 0; it < niter; ++it) {
        cp_wait<1>();
        __syncthreads();
        if (it + 2 < niter) issue(it + 2);
        cp_commit();
        compute(it % 3);
    }

    // ---- epilogue ----
    const int region = (ACT == 2) ? (bn / E_) : 0;   // 0=q 1=k 2=v
    const int hd0    = (ACT == 2) ? (bn % E_) : 0;
    const bool addb  = (ACT != 0) || (blockIdx.z == 0);
    float* Cz = (float*)Cout + (ACT == 0 ? (size_t)blockIdx.z * M * N : 0);
    #pragma unroll
    for (int i = 0; i < 4; i++) {
        #pragma unroll
        for (int j = 0; j < 4; j++) {
            int row = bm + wm + i * 16 + (lane >> 2);
            int col = bn + wn + j * 8 + (lane & 3) * 2;
            float2 bv = make_float2(0.f, 0.f);
            if (bias && addb) bv = *(const float2*)&bias[col];
            float o[2][2] = {{acc[i][j][0] + bv.x, acc[i][j][1] + bv.y},
                             {acc[i][j][2] + bv.x, acc[i][j][3] + bv.y}};
            if (ACT == 0) {
                *(float2*)&Cz[(size_t)row * N + col]       = make_float2(o[0][0], o[0][1]);
                *(float2*)&Cz[(size_t)(row + 8) * N + col] = make_float2(o[1][0], o[1][1]);
            } else if (ACT == 1) {
                __half* C = (__half*)Cout;
                *(__half2*)&C[(size_t)row * N + col] =
                    __floats2half2_rn(gelu_exact(o[0][0]), gelu_exact(o[0][1]));
                *(__half2*)&C[(size_t)(row + 8) * N + col] =
                    __floats2half2_rn(gelu_exact(o[1][0]), gelu_exact(o[1][1]));
            } else {
                int hd = hd0 + wn + j * 8 + (lane & 3) * 2;
                int h = hd >> 6, d = hd & 63;
                #pragma unroll
                for (int r = 0; r < 2; r++) {
                    int rr = row + r * 8;
                    int b = rr >> 9, s = rr & 511;
                    int z = b * H_ + h;
                    __half2 val = __floats2half2_rn(o[r][0], o[r][1]);
                    if (region == 0) {
                        *(__half2*)&qp[((size_t)z * S_ + s) * D_ + d] = val;
                    } else if (region == 1) {
                        *(__half2*)&kp[((size_t)z * S_ + s) * D_ + d] = val;
                    } else {
                        vp[((size_t)z * D_ + d)     * S_ + s] = __low2half(val);
                        vp[((size_t)z * D_ + d + 1) * S_ + s] = __high2half(val);
                    }
                }
            }
        }
    }
}

// ---------------- flash attention v2 (R12: 64 q-rows, 128 threads) ----------
#define FA2_SMEM 64512     // Q 9216 + 3*K 27648 + 3*V 27648 bytes

__global__ void __launch_bounds__(128, 2) flash2_kernel(
    const __half* __restrict__ q, const __half* __restrict__ k,
    const __half* __restrict__ vt, __half* __restrict__ merged)
{
    extern __shared__ __half hs[];
    __half* Qs = hs;                     // 64 x 72
    __half* Ks = hs + 4608;              // 3 x (64 x 72)
    __half* Vs = hs + 4 * 4608;          // 3 x (64 x 72)

    const int tid = threadIdx.x, lane = tid & 31, warp = tid >> 5;
    const int z = blockIdx.y, q0 = blockIdx.x * 64;
    const __half* qg = q  + (size_t)z * S_ * D_ + (size_t)q0 * D_;
    const __half* kg = k  + (size_t)z * S_ * D_;
    const __half* vg = vt + (size_t)z * D_ * S_;

    auto loadKV = [&](int t) {
        __half* dk = Ks + (t % 3) * 4608;
        __half* dv = Vs + (t % 3) * 4608;
        const __half* sk = kg + (size_t)t * 64 * 64;
        #pragma unroll
        for (int r = 0; r < 4; r++) {
            int ch = tid + r * 128;
            int row = ch >> 3, c = ch & 7;
            cp_async16(dk + row * 72 + c * 8, sk + row * 64 + c * 8);
            cp_async16(dv + row * 72 + c * 8, vg + row * 512 + t * 64 + c * 8);
        }
    };

    #pragma unroll
    for (int r = 0; r < 4; r++) {
        int ch = tid + r * 128;
        int row = ch >> 3, c = ch & 7;
        cp_async16(Qs + row * 72 + c * 8, qg + row * 64 + c * 8);
    }
    loadKV(0); cp_commit();
    loadKV(1); cp_commit();

    uint32_t qa[4][4];
    float Oacc[8][4] = {};
    float m0 = -INFINITY, m1 = -INFINITY, l0 = 0.f, l1 = 0.f;

    const int r0 = warp * 16 + (lane >> 2);
    const int ccol = (lane & 3) * 2;

    for (int t = 0; t < 8; t++) {
        cp_wait<1>();
        __syncthreads();
        if (t == 0) {
            #pragma unroll
            for (int kc = 0; kc < 4; kc++) {
                qa[kc][0] = *(const uint32_t*)(Qs + r0 * 72 + kc * 16 + ccol);
                qa[kc][1] = *(const uint32_t*)(Qs + (r0 + 8) * 72 + kc * 16 + ccol);
                qa[kc][2] = *(const uint32_t*)(Qs + r0 * 72 + kc * 16 + 8 + ccol);
                qa[kc][3] = *(const uint32_t*)(Qs + (r0 + 8) * 72 + kc * 16 + 8 + ccol);
            }
        }
        if (t + 2 < 8) loadKV(t + 2);
        cp_commit();

        const __half* Kt = Ks + (t % 3) * 4608;
        const __half* Vb = Vs + (t % 3) * 4608;

        float sacc[8][4] = {};
        #pragma unroll
        for (int kc = 0; kc < 4; kc++) {
            uint32_t kb[8][2];
            #pragma unroll
            for (int nt = 0; nt < 8; nt++) {
                const __half* pk = Kt + (nt * 8 + (lane >> 2)) * 72 + kc * 16 + ccol;
                kb[nt][0] = *(const uint32_t*)pk;
                kb[nt][1] = *(const uint32_t*)(pk + 8);
            }
            #pragma unroll
            for (int nt = 0; nt < 8; nt++)
                mma_f16(sacc[nt], qa[kc], kb[nt]);
        }

        float mt0 = -INFINITY, mt1 = -INFINITY;
        #pragma unroll
        for (int nt = 0; nt < 8; nt++) {
            mt0 = fmaxf(mt0, fmaxf(sacc[nt][0], sacc[nt][1]));
            mt1 = fmaxf(mt1, fmaxf(sacc[nt][2], sacc[nt][3]));
        }
        mt0 = fmaxf(mt0, __shfl_xor_sync(~0u, mt0, 1));
        mt0 = fmaxf(mt0, __shfl_xor_sync(~0u, mt0, 2));
        mt1 = fmaxf(mt1, __shfl_xor_sync(~0u, mt1, 1));
        mt1 = fmaxf(mt1, __shfl_xor_sync(~0u, mt1, 2));
        float mn0 = fmaxf(m0, mt0), mn1 = fmaxf(m1, mt1);
        float sc0 = expf(m0 - mn0), sc1 = expf(m1 - mn1);
        m0 = mn0; m1 = mn1;

        float ts0 = 0.f, ts1 = 0.f;
        uint32_t ph[8][2];
        #pragma unroll
        for (int nt = 0; nt < 8; nt++) {
            float p0 = expf(sacc[nt][0] - mn0), p1 = expf(sacc[nt][1] - mn0);
            float p2 = expf(sacc[nt][2] - mn1), p3 = expf(sacc[nt][3] - mn1);
            ts0 += p0 + p1; ts1 += p2 + p3;
            __half2 h0 = __floats2half2_rn(p0, p1);
            __half2 h1 = __floats2half2_rn(p2, p3);
            ph[nt][0] = *(uint32_t*)&h0;
            ph[nt][1] = *(uint32_t*)&h1;
        }
        ts0 += __shfl_xor_sync(~0u, ts0, 1); ts0 += __shfl_xor_sync(~0u, ts0, 2);
        ts1 += __shfl_xor_sync(~0u, ts1, 1); ts1 += __shfl_xor_sync(~0u, ts1, 2);
        l0 = l0 * sc0 + ts0;
        l1 = l1 * sc1 + ts1;
        #pragma unroll
        for (int nt = 0; nt < 8; nt++) {
            Oacc[nt][0] *= sc0; Oacc[nt][1] *= sc0;
            Oacc[nt][2] *= sc1; Oacc[nt][3] *= sc1;
        }

        #pragma unroll
        for (int kc = 0; kc < 4; kc++) {
            uint32_t vb[8][2];
            #pragma unroll
            for (int nt = 0; nt < 8; nt++) {
                const __half* pv = Vb + (nt * 8 + (lane >> 2)) * 72 + kc * 16 + ccol;
                vb[nt][0] = *(const uint32_t*)pv;
                vb[nt][1] = *(const uint32_t*)(pv + 8);
            }
            uint32_t af[4] = {ph[2*kc][0], ph[2*kc][1], ph[2*kc+1][0], ph[2*kc+1][1]};
            #pragma unroll
            for (int nt = 0; nt < 8; nt++)
                mma_f16(Oacc[nt], af, vb[nt]);
        }
    }

    const int b = z / H_, h = z % H_;
    float inv0 = SCALE_INV / l0, inv1 = SCALE_INV / l1;
    size_t s0 = (size_t)(b * S_ + q0 + r0) * E_ + h * 64 + ccol;
    size_t s1 = (size_t)(b * S_ + q0 + r0 + 8) * E_ + h * 64 + ccol;
    #pragma unroll
    for (int nt = 0; nt < 8; nt++) {
        *(__half2*)&merged[s0 + nt * 8] =
            __floats2half2_rn(Oacc[nt][0] * inv0, Oacc[nt][1] * inv0);
        *(__half2*)&merged[s1 + nt * 8] =
            __floats2half2_rn(Oacc[nt][2] * inv1, Oacc[nt][3] * inv1);
    }
}

// ---------------- block reductions ----------------
__device__ __forceinline__ float block_reduce(float v) {
    __shared__ float sh[8];
    int lane = threadIdx.x & 31, wid = threadIdx.x >> 5;
    #pragma unroll
    for (int o = 16; o; o >>= 1) v += __shfl_xor_sync(0xffffffffu, v, o);
    if (lane == 0) sh[wid] = v;
    __syncthreads();
    if (wid == 0) {
        v = (lane < 8) ? sh[lane] : 0.0f;
        #pragma unroll
        for (int o = 4; o; o >>= 1) v += __shfl_xor_sync(0xffffffffu, v, o);
        if (lane == 0) sh[0] = v;
    }
    __syncthreads();
    float r = sh[0];
    __syncthreads();
    return r;
}

__global__ __launch_bounds__(256) void ln_kernel(
    const float* __restrict__ in, const float* __restrict__ g,
    const float* __restrict__ bb, __half* __restrict__ out)
{
    long long base = (long long)blockIdx.x * E_;
    int t = threadIdx.x;
    float v[3];
    #pragma unroll
    for (int i = 0; i < 3; i++) v[i] = in[base + t + i*256];
    float s  = block_reduce(v[0] + v[1] + v[2]);
    float sq = block_reduce(v[0]*v[0] + v[1]*v[1] + v[2]*v[2]);
    float mean = s * (1.0f/E_);
    float rstd = rsqrtf(sq * (1.0f/E_) - mean*mean + 1e-5f);
    #pragma unroll
    for (int i = 0; i < 3; i++) {
        int c = t + i*256;
        out[base + c] = __float2half_rn((v[i] - mean) * rstd * g[c] + bb[c]);
    }
}

// in = p0 + p1 (split-K partials)
__global__ __launch_bounds__(256) void ln2_ln3_kernel(
    const float* __restrict__ p0, const float* __restrict__ p1,
    const float* __restrict__ x,
    const float* __restrict__ g2, const float* __restrict__ b2,
    const float* __restrict__ g3, const float* __restrict__ b3,
    float* __restrict__ r1, __half* __restrict__ f)
{
    long long base = (long long)blockIdx.x * E_;
    int t = threadIdx.x;
    float v[3];
    #pragma unroll
    for (int i = 0; i < 3; i++) v[i] = p0[base + t + i*256] + p1[base + t + i*256];
    float s  = block_reduce(v[0] + v[1] + v[2]);
    float sq = block_reduce(v[0]*v[0] + v[1]*v[1] + v[2]*v[2]);
    float mean = s * (1.0f/E_);
    float rstd = rsqrtf(sq * (1.0f/E_) - mean*mean + 1e-5f);
    #pragma unroll
    for (int i = 0; i < 3; i++) {
        int c = t + i*256;
        v[i] = (v[i] - mean) * rstd * g2[c] + b2[c] + x[base + c];
        r1[base + c] = v[i];
    }
    float s2  = block_reduce(v[0] + v[1] + v[2]);
    float sq2 = block_reduce(v[0]*v[0] + v[1]*v[1] + v[2]*v[2]);
    float mean2 = s2 * (1.0f/E_);
    float rstd2 = rsqrtf(sq2 * (1.0f/E_) - mean2*mean2 + 1e-5f);
    #pragma unroll
    for (int i = 0; i < 3; i++) {
        int c = t + i*256;
        f[base + c] = __float2half_rn((v[i] - mean2) * rstd2 * g3[c] + b3[c]);
    }
}

// f2 = p0 + p1 (split-K partials)
__global__ __launch_bounds__(256) void ln4_ln1_kernel(
    const float* __restrict__ p0, const float* __restrict__ p1,
    const float* __restrict__ r1, const float* __restrict__ x,
    const float* __restrict__ g4, const float* __restrict__ b4,
    const float* __restrict__ g1, const float* __restrict__ b1,
    float* __restrict__ xout, __half* __restrict__ hout)
{
    long long base = (long long)blockIdx.x * E_;
    int t = threadIdx.x;
    float v[3];
    #pragma unroll
    for (int i = 0; i < 3; i++) v[i] = p0[base + t + i*256] + p1[base + t + i*256];
    float s  = block_reduce(v[0] + v[1] + v[2]);
    float sq = block_reduce(v[0]*v[0] + v[1]*v[1] + v[2]*v[2]);
    float mean = s * (1.0f/E_);
    float rstd = rsqrtf(sq * (1.0f/E_) - mean*mean + 1e-5f);
    #pragma unroll
    for (int i = 0; i < 3; i++) {
        int c = t + i*256;
        v[i] = (v[i] - mean) * rstd * g4[c] + b4[c] + r1[base + c] + x[base + c];
        xout[base + c] = v[i];
    }
    if (g1 == nullptr) return;
    float s2  = block_reduce(v[0] + v[1] + v[2]);
    float sq2 = block_reduce(v[0]*v[0] + v[1]*v[1] + v[2]*v[2]);
    float mean2 = s2 * (1.0f/E_);
    float rstd2 = rsqrtf(sq2 * (1.0f/E_) - mean2*mean2 + 1e-5f);
    #pragma unroll
    for (int i = 0; i < 3; i++) {
        int c = t + i*256;
        hout[base + c] = __float2half_rn((v[i] - mean2) * rstd2 * g1[c] + b1[c]);
    }
}

// -------- weight transpose + halve: in [L][K][N] f32 -> out [L][N][K] half --
__global__ __launch_bounds__(256) void transpose_h(
    const float* __restrict__ in, __half* __restrict__ out, int K, int N)
{
    __shared__ float t[32][33];
    size_t lofs = (size_t)blockIdx.z * K * N;
    in += lofs; out += lofs;
    int n0 = blockIdx.x * 32, k0 = blockIdx.y * 32;
    int tx = threadIdx.x & 31, ty = threadIdx.x >> 5;   // 32 x 8
    #pragma unroll
    for (int i = 0; i < 4; i++)
        t[ty + i*8][tx] = in[(size_t)(k0 + ty + i*8) * N + n0 + tx];
    __syncthreads();
    #pragma unroll
    for (int i = 0; i < 4; i++)
        out[(size_t)(n0 + ty + i*8) * K + k0 + tx] = __float2half_rn(t[tx][ty + i*8]);
}

// -------- qkv weight transpose with column permutation ----------------------
__global__ __launch_bounds__(256) void transpose_qkv(
    const float* __restrict__ in, __half* __restrict__ out)
{
    __shared__ float t[32][33];
    size_t lofs = (size_t)blockIdx.z * E_ * E3_;
    in += lofs; out += lofs;
    int n0 = blockIdx.x * 32, k0 = blockIdx.y * 32;
    int tx = threadIdx.x & 31, ty = threadIdx.x >> 5;
    int c_reg = n0 / E_;
    #pragma unroll
    for (int i = 0; i < 4; i++) {
        int nn = n0 + tx;
        int n_orig = (nn % E_) * 3 + c_reg;
        t[ty + i*8][tx] = in[(size_t)(k0 + ty + i*8) * E3_ + n_orig];
    }
    __syncthreads();
    #pragma unroll
    for (int i = 0; i < 4; i++)
        out[(size_t)(n0 + ty + i*8) * E_ + k0 + tx] = __float2half_rn(t[tx][ty + i*8]);
}

__global__ __launch_bounds__(256) void permute_bias(
    const float* __restrict__ in, float* __restrict__ out)
{
    int i = blockIdx.x * 256 + threadIdx.x;
    int l = i / E3_, n = i % E3_;
    int n_orig = (n % E_) * 3 + n / E_;
    out[i] = in[l * E3_ + n_orig];
}

// ---------------- host orchestration ----------------
extern "C" void kernel_launch(void* const* d_in, const int* in_sizes, int n_in,
                              void* d_out, int out_size)
{
    (void)in_sizes; (void)n_in; (void)out_size;

    const float* x_in  = (const float*)d_in[0];
    const float* Wqkv  = (const float*)d_in[1];
    const float* bqkv  = (const float*)d_in[2];
    const float* Wp    = (const float*)d_in[3];
    const float* bp    = (const float*)d_in[4];
    const float* W1    = (const float*)d_in[5];
    const float* b1    = (const float*)d_in[6];
    const float* W2    = (const float*)d_in[7];
    const float* b2    = (const float*)d_in[8];
    const float* g1    = (const float*)d_in[9];
    const float* be1   = (const float*)d_in[10];
    const float* g2    = (const float*)d_in[11];
    const float* be2   = (const float*)d_in[12];
    const float* g3    = (const float*)d_in[13];
    const float* be3   = (const float*)d_in[14];
    const float* g4    = (const float*)d_in[15];
    const float* be4   = (const float*)d_in[16];

    static bool attr_done = false;
    if (!attr_done) {
        cudaFuncSetAttribute(gemm_h<0>,
                             cudaFuncAttributeMaxDynamicSharedMemorySize, GH_SMEM);
        cudaFuncSetAttribute(gemm_h<1>,
                             cudaFuncAttributeMaxDynamicSharedMemorySize, GH_SMEM);
        cudaFuncSetAttribute(gemm_h<2>,
                             cudaFuncAttributeMaxDynamicSharedMemorySize, GH_SMEM);
        cudaFuncSetAttribute(flash2_kernel,
                             cudaFuncAttributeMaxDynamicSharedMemorySize, FA2_SMEM);
        attr_done = true;
    }

    __half *p_h, *p_q, *p_k, *p_v, *p_merged, *p_f, *p_ff;
    float *p_oproj, *p_r1, *p_f2, *p_x, *p_bqkv;
    __half *w_qkv, *w_p, *w_1, *w_2;
    cudaGetSymbolAddress((void**)&p_h, g_h);
    cudaGetSymbolAddress((void**)&p_q, g_q);
    cudaGetSymbolAddress((void**)&p_k, g_k);
    cudaGetSymbolAddress((void**)&p_v, g_v);
    cudaGetSymbolAddress((void**)&p_merged, g_merged);
    cudaGetSymbolAddress((void**)&p_oproj, g_oproj);
    cudaGetSymbolAddress((void**)&p_r1, g_r1);
    cudaGetSymbolAddress((void**)&p_f, g_f);
    cudaGetSymbolAddress((void**)&p_ff, g_ff);
    cudaGetSymbolAddress((void**)&p_f2, g_f2);
    cudaGetSymbolAddress((void**)&p_x, g_x);
    cudaGetSymbolAddress((void**)&p_bqkv, g_bqkv_p);
    cudaGetSymbolAddress((void**)&w_qkv, g_Wqkv_t);
    cudaGetSymbolAddress((void**)&w_p, g_Wp_t);
    cudaGetSymbolAddress((void**)&w_1, g_W1_t);
    cudaGetSymbolAddress((void**)&w_2, g_W2_t);

    // pre-transpose + halve all weights (once per launch)
    transpose_qkv<<<dim3(E3_/32, E_/32, L_), 256>>>(Wqkv, w_qkv);
    permute_bias<<<(L_*E3_)/256, 256>>>(bqkv, p_bqkv);
    transpose_h<<<dim3(E_/32,  E_/32, L_), 256>>>(Wp,   w_p,   E_, E_);
    transpose_h<<<dim3(FF_/32, E_/32, L_), 256>>>(W1,   w_1,   E_, FF_);
    transpose_h<<<dim3(E_/32, FF_/32, L_), 256>>>(W2,   w_2,   FF_, E_);

    cudaMemcpyAsync(p_x, x_in, (size_t)NTOK * E_ * sizeof(float),
                    cudaMemcpyDeviceToDevice, 0);

    // h = LN1_0(x)
    ln_kernel<<<NTOK, 256>>>(p_x, g1, be1, p_h);

    const size_t PSZ = (size_t)NTOK * E_;   // partial-buffer stride

    for (int l = 0; l < L_; ++l) {
        const __half* Wqkv_l = w_qkv + (size_t)l * E_ * E3_;
        const float*  bqkv_l = p_bqkv + (size_t)l * E3_;
        const __half* Wp_l   = w_p  + (size_t)l * E_ * E_;
        const float*  bp_l   = bp   + (size_t)l * E_;
        const __half* W1_l   = w_1  + (size_t)l * E_ * FF_;
        const float*  b1_l   = b1   + (size_t)l * FF_;
        const __half* W2_l   = w_2  + (size_t)l * FF_ * E_;
        const float*  b2_l   = b2   + (size_t)l * E_;
        const float* g2_l = g2 + (size_t)l * E_, *be2_l = be2 + (size_t)l * E_;
        const float* g3_l = g3 + (size_t)l * E_, *be3_l = be3 + (size_t)l * E_;
        const float* g4_l = g4 + (size_t)l * E_, *be4_l = be4 + (size_t)l * E_;

        // qkv = h @ Wqkv_perm + bqkv_perm -> q | k | v regions (half)
        gemm_h<2><<<dim3(E3_/128, NTOK/128, 1), 256, GH_SMEM>>>(
            p_h, Wqkv_l, bqkv_l, nullptr, NTOK, E3_, E_, E_, p_q, p_k, p_v);
        // fused flash attention (online softmax) -> merged (half)
        flash2_kernel<<<dim3(S_/64, BH), 128, FA2_SMEM>>>(p_q, p_k, p_v, p_merged);
        // oproj partials = merged @ Wp (+bp on z=0), split-K=2 -> 192 CTAs
        gemm_h<0><<<dim3(E_/128, NTOK/128, 2), 256, GH_SMEM>>>(
            p_merged, Wp_l, bp_l, p_oproj, NTOK, E_, E_/2, E_,
            nullptr, nullptr, nullptr);
        // r1 = LN2(oproj0+oproj1) + x ; f = LN3(r1) (half)
        ln2_ln3_kernel<<<NTOK, 256>>>(p_oproj, p_oproj + PSZ, p_x,
                                      g2_l, be2_l, g3_l, be3_l, p_r1, p_f);
        // ff = gelu(f @ W1 + b1) (half)
        gemm_h<1><<<dim3(FF_/128, NTOK/128, 1), 256, GH_SMEM>>>(
            p_f, W1_l, b1_l, p_ff, NTOK, FF_, E_, E_, nullptr, nullptr, nullptr);
        // f2 partials = ff @ W2 (+b2 on z=0), split-K=2 -> 192 CTAs
        gemm_h<0><<<dim3(E_/128, NTOK/128, 2), 256, GH_SMEM>>>(
            p_ff, W2_l, b2_l, p_f2, NTOK, E_, FF_/2, FF_,
            nullptr, nullptr, nullptr);
        // x = LN4(f20+f21) + r1 + x ; h = LN1_{l+1}(x) (half)
        const float* g1n  = (l + 1 < L_) ? g1  + (size_t)(l + 1) * E_ : nullptr;
        const float* be1n = (l + 1 < L_) ? be1 + (size_t)(l + 1) * E_ : nullptr;
        ln4_ln1_kernel<<<NTOK, 256>>>(p_f2, p_f2 + PSZ, p_r1, p_x,
                                      g4_l, be4_l, g1n, be1n, p_x, p_h);
    }

    cudaMemcpyAsync(d_out, p_x, (size_t)NTOK * E_ * sizeof(float),
                    cudaMemcpyDeviceToDevice, 0);
}

// round 17
// speedup vs baseline: 1.1459x; 1.0014x over previous
#include <cuda_runtime.h>
#include <cuda_fp16.h>
#include <math.h>
#include <stdint.h>

#define B_   4
#define S_   512
#define E_   768
#define H_   12
#define D_   64
#define FF_  3072
#define L_   12
#define NTOK (B_*S_)     // 2048
#define BH   (B_*H_)     // 48
#define E3_  (3*E_)      // 2304

#define SCALE_INV 0.03608439182435161f   // 1/sqrt(768), applied AFTER softmax

// ---------------- scratch (static __device__, no allocation) ----------------
__device__ __half g_h[NTOK*E_];
__device__ __half g_q[BH*S_*D_];        // [z][s][d]
__device__ __half g_k[BH*S_*D_];        // [z][s][d]
__device__ __half g_v[BH*D_*S_];        // [z][d][s]  (transposed for PV)
__device__ __half g_merged[NTOK*E_];
__device__ float  g_oproj[2*NTOK*E_];   // split-K partials
__device__ float  g_r1[NTOK*E_];
__device__ __half g_f[NTOK*E_];
__device__ __half g_ff[NTOK*FF_];
__device__ float  g_f2[2*NTOK*E_];      // split-K partials
__device__ float  g_x[NTOK*E_];
// fp16 + transposed weight copies ([N][K] K-major per layer)
__device__ __half g_Wqkv_t[(size_t)L_*E_*E3_];   // qkv: column-permuted (q|k|v)
__device__ float  g_bqkv_p[(size_t)L_*E3_];      // permuted bias
__device__ __half g_Wp_t[(size_t)L_*E_*E_];
__device__ __half g_W1_t[(size_t)L_*E_*FF_];
__device__ __half g_W2_t[(size_t)L_*FF_*E_];

// ---------------- helpers ----------------
__device__ __forceinline__ void mma_f16(float* c, const uint32_t* a, const uint32_t* b) {
    asm volatile(
        "mma.sync.aligned.m16n8k16.row.col.f32.f16.f16.f32 "
        "{%0,%1,%2,%3}, {%4,%5,%6,%7}, {%8,%9}, {%0,%1,%2,%3};"
        : "+f"(c[0]), "+f"(c[1]), "+f"(c[2]), "+f"(c[3])
        : "r"(a[0]), "r"(a[1]), "r"(a[2]), "r"(a[3]), "r"(b[0]), "r"(b[1]));
}

__device__ __forceinline__ void cp_async16(void* smem, const void* gmem) {
    uint32_t s = (uint32_t)__cvta_generic_to_shared(smem);
    asm volatile("cp.async.cg.shared.global [%0], [%1], 16;\n" :: "r"(s), "l"(gmem));
}
__device__ __forceinline__ void cp_commit() {
    asm volatile("cp.async.commit_group;\n");
}
template<int N> __device__ __forceinline__ void cp_wait() {
    asm volatile("cp.async.wait_group %0;\n" :: "n"(N));
}

__device__ __forceinline__ float gelu_exact(float x) {
    return 0.5f * x * (1.0f + erff(x * 0.7071067811865476f));
}

// ---------------- fp16 tensor-core GEMM, cp.async 3-stage, BK=64 ------------
// C = A[M,Kfull](half) @ Bt[N,Kfull](half) + bias(f32), over K slice
// [blockIdx.z*Ksub, (blockIdx.z+1)*Ksub). ACT==0 writes partial to
// C + blockIdx.z*M*N, bias only from z==0.
// ACT: 0 plain f32 out (split-K capable); 1 gelu -> half; 2 qkv-split (perm).
#define GH_STAGE 36864                       // 18432 A + 18432 B
#define GH_SMEM  (3 * GH_STAGE)              // 110592

template<int ACT>
__global__ void __launch_bounds__(256, 2) gemm_h(
    const __half* __restrict__ A, const __half* __restrict__ Bt,
    const float* __restrict__ bias, void* __restrict__ Cout,
    int M, int N, int Ksub, int Kfull,
    __half* __restrict__ qp, __half* __restrict__ kp, __half* __restrict__ vp)
{
    extern __shared__ char smem[];
    const int tid  = threadIdx.x;
    const int lane = tid & 31;
    const int warp = tid >> 5;
    const int wm = (warp & 1) * 64;           // WRM=2
    const int wn = (warp >> 1) * 32;          // WRN=4
    const int bm = blockIdx.y * 128;
    const int bn = blockIdx.x * 128;
    const int koff = blockIdx.z * Ksub;
    const int niter = Ksub / 64;

    float acc[4][4][4] = {};

    auto issue = [&](int s) {
        char* st = smem + (s % 3) * GH_STAGE;
        int k0 = koff + s * 64;
        #pragma unroll
        for (int r = 0; r < 4; r++) {
            int ch = tid + r * 256;
            int row = ch >> 3, kq = ch & 7;
            cp_async16(st + row * 144 + kq * 16,
                       &A[(size_t)(bm + row) * Kfull + k0 + kq * 8]);
            cp_async16(st + 18432 + row * 144 + kq * 16,
                       &Bt[(size_t)(bn + row) * Kfull + k0 + kq * 8]);
        }
    };

    auto compute = [&](int buf) {
        const uint32_t* Ab = (const uint32_t*)(smem + buf * GH_STAGE);
        const uint32_t* Bb = (const uint32_t*)(smem + buf * GH_STAGE + 18432);
        #pragma unroll
        for (int kk = 0; kk < 4; kk++) {            // four k16 slices per BK=64
            int c0 = kk * 8 + (lane & 3);
            uint32_t af[4][4];
            #pragma unroll
            for (int i = 0; i < 4; i++) {
                const uint32_t* p = &Ab[(wm + i * 16 + (lane >> 2)) * 36 + c0];
                af[i][0] = p[0];
                af[i][1] = p[288];      // +8 rows * 36 words
                af[i][2] = p[4];        // +8 halves
                af[i][3] = p[292];
            }
            uint32_t bf[4][2];
            #pragma unroll
            for (int j = 0; j < 4; j++) {
                const uint32_t* p = &Bb[(wn + j * 8 + (lane >> 2)) * 36 + c0];
                bf[j][0] = p[0];
                bf[j][1] = p[4];        // k+8
            }
            #pragma unroll
            for (int i = 0; i < 4; i++)
                #pragma unroll
                for (int j = 0; j < 4; j++)
                    mma_f16(acc[i][j], af[i], bf[j]);
        }
    };

    #pragma unroll
    for (int s = 0; s < 2; s++) { if (s < niter) issue(s); cp_commit(); }
    for (int it = 0; it < niter; ++it) {
        cp_wait<1>();
        __syncthreads();
        if (it + 2 < niter) issue(it + 2);
        cp_commit();
        compute(it % 3);
    }

    // ---- epilogue ----
    const int region = (ACT == 2) ? (bn / E_) : 0;   // 0=q 1=k 2=v
    const int hd0    = (ACT == 2) ? (bn % E_) : 0;
    const bool addb  = (ACT != 0) || (blockIdx.z == 0);
    float* Cz = (float*)Cout + (ACT == 0 ? (size_t)blockIdx.z * M * N : 0);
    #pragma unroll
    for (int i = 0; i < 4; i++) {
        #pragma unroll
        for (int j = 0; j < 4; j++) {
            int row = bm + wm + i * 16 + (lane >> 2);
            int col = bn + wn + j * 8 + (lane & 3) * 2;
            float2 bv = make_float2(0.f, 0.f);
            if (bias && addb) bv = *(const float2*)&bias[col];
            float o[2][2] = {{acc[i][j][0] + bv.x, acc[i][j][1] + bv.y},
                             {acc[i][j][2] + bv.x, acc[i][j][3] + bv.y}};
            if (ACT == 0) {
                *(float2*)&Cz[(size_t)row * N + col]       = make_float2(o[0][0], o[0][1]);
                *(float2*)&Cz[(size_t)(row + 8) * N + col] = make_float2(o[1][0], o[1][1]);
            } else if (ACT == 1) {
                __half* C = (__half*)Cout;
                *(__half2*)&C[(size_t)row * N + col] =
                    __floats2half2_rn(gelu_exact(o[0][0]), gelu_exact(o[0][1]));
                *(__half2*)&C[(size_t)(row + 8) * N + col] =
                    __floats2half2_rn(gelu_exact(o[1][0]), gelu_exact(o[1][1]));
            } else {
                int hd = hd0 + wn + j * 8 + (lane & 3) * 2;
                int h = hd >> 6, d = hd & 63;
                #pragma unroll
                for (int r = 0; r < 2; r++) {
                    int rr = row + r * 8;
                    int b = rr >> 9, s = rr & 511;
                    int z = b * H_ + h;
                    __half2 val = __floats2half2_rn(o[r][0], o[r][1]);
                    if (region == 0) {
                        *(__half2*)&qp[((size_t)z * S_ + s) * D_ + d] = val;
                    } else if (region == 1) {
                        *(__half2*)&kp[((size_t)z * S_ + s) * D_ + d] = val;
                    } else {
                        vp[((size_t)z * D_ + d)     * S_ + s] = __low2half(val);
                        vp[((size_t)z * D_ + d + 1) * S_ + s] = __high2half(val);
                    }
                }
            }
        }
    }
}

// ---------------- flash attention v2 (64 q-rows, 128 threads, 3 CTAs/SM) ----
#define FA2_SMEM 64512     // Q 9216 + 3*K 27648 + 3*V 27648 bytes

__global__ void __launch_bounds__(128, 3) flash2_kernel(
    const __half* __restrict__ q, const __half* __restrict__ k,
    const __half* __restrict__ vt, __half* __restrict__ merged)
{
    extern __shared__ __half hs[];
    __half* Qs = hs;                     // 64 x 72
    __half* Ks = hs + 4608;              // 3 x (64 x 72)
    __half* Vs = hs + 4 * 4608;          // 3 x (64 x 72)

    const int tid = threadIdx.x, lane = tid & 31, warp = tid >> 5;
    const int z = blockIdx.y, q0 = blockIdx.x * 64;
    const __half* qg = q  + (size_t)z * S_ * D_ + (size_t)q0 * D_;
    const __half* kg = k  + (size_t)z * S_ * D_;
    const __half* vg = vt + (size_t)z * D_ * S_;

    auto loadKV = [&](int t) {
        __half* dk = Ks + (t % 3) * 4608;
        __half* dv = Vs + (t % 3) * 4608;
        const __half* sk = kg + (size_t)t * 64 * 64;
        #pragma unroll
        for (int r = 0; r < 4; r++) {
            int ch = tid + r * 128;
            int row = ch >> 3, c = ch & 7;
            cp_async16(dk + row * 72 + c * 8, sk + row * 64 + c * 8);
            cp_async16(dv + row * 72 + c * 8, vg + row * 512 + t * 64 + c * 8);
        }
    };

    #pragma unroll
    for (int r = 0; r < 4; r++) {
        int ch = tid + r * 128;
        int row = ch >> 3, c = ch & 7;
        cp_async16(Qs + row * 72 + c * 8, qg + row * 64 + c * 8);
    }
    loadKV(0); cp_commit();
    loadKV(1); cp_commit();

    uint32_t qa[4][4];
    float Oacc[8][4] = {};
    float m0 = -INFINITY, m1 = -INFINITY, l0 = 0.f, l1 = 0.f;

    const int r0 = warp * 16 + (lane >> 2);
    const int ccol = (lane & 3) * 2;

    for (int t = 0; t < 8; t++) {
        cp_wait<1>();
        __syncthreads();
        if (t == 0) {
            #pragma unroll
            for (int kc = 0; kc < 4; kc++) {
                qa[kc][0] = *(const uint32_t*)(Qs + r0 * 72 + kc * 16 + ccol);
                qa[kc][1] = *(const uint32_t*)(Qs + (r0 + 8) * 72 + kc * 16 + ccol);
                qa[kc][2] = *(const uint32_t*)(Qs + r0 * 72 + kc * 16 + 8 + ccol);
                qa[kc][3] = *(const uint32_t*)(Qs + (r0 + 8) * 72 + kc * 16 + 8 + ccol);
            }
        }
        if (t + 2 < 8) loadKV(t + 2);
        cp_commit();

        const __half* Kt = Ks + (t % 3) * 4608;
        const __half* Vb = Vs + (t % 3) * 4608;

        float sacc[8][4] = {};
        #pragma unroll
        for (int kc = 0; kc < 4; kc++) {
            uint32_t kb[8][2];
            #pragma unroll
            for (int nt = 0; nt < 8; nt++) {
                const __half* pk = Kt + (nt * 8 + (lane >> 2)) * 72 + kc * 16 + ccol;
                kb[nt][0] = *(const uint32_t*)pk;
                kb[nt][1] = *(const uint32_t*)(pk + 8);
            }
            #pragma unroll
            for (int nt = 0; nt < 8; nt++)
                mma_f16(sacc[nt], qa[kc], kb[nt]);
        }

        float mt0 = -INFINITY, mt1 = -INFINITY;
        #pragma unroll
        for (int nt = 0; nt < 8; nt++) {
            mt0 = fmaxf(mt0, fmaxf(sacc[nt][0], sacc[nt][1]));
            mt1 = fmaxf(mt1, fmaxf(sacc[nt][2], sacc[nt][3]));
        }
        mt0 = fmaxf(mt0, __shfl_xor_sync(~0u, mt0, 1));
        mt0 = fmaxf(mt0, __shfl_xor_sync(~0u, mt0, 2));
        mt1 = fmaxf(mt1, __shfl_xor_sync(~0u, mt1, 1));
        mt1 = fmaxf(mt1, __shfl_xor_sync(~0u, mt1, 2));
        float mn0 = fmaxf(m0, mt0), mn1 = fmaxf(m1, mt1);
        float sc0 = expf(m0 - mn0), sc1 = expf(m1 - mn1);
        m0 = mn0; m1 = mn1;

        float ts0 = 0.f, ts1 = 0.f;
        uint32_t ph[8][2];
        #pragma unroll
        for (int nt = 0; nt < 8; nt++) {
            float p0 = expf(sacc[nt][0] - mn0), p1 = expf(sacc[nt][1] - mn0);
            float p2 = expf(sacc[nt][2] - mn1), p3 = expf(sacc[nt][3] - mn1);
            ts0 += p0 + p1; ts1 += p2 + p3;
            __half2 h0 = __floats2half2_rn(p0, p1);
            __half2 h1 = __floats2half2_rn(p2, p3);
            ph[nt][0] = *(uint32_t*)&h0;
            ph[nt][1] = *(uint32_t*)&h1;
        }
        ts0 += __shfl_xor_sync(~0u, ts0, 1); ts0 += __shfl_xor_sync(~0u, ts0, 2);
        ts1 += __shfl_xor_sync(~0u, ts1, 1); ts1 += __shfl_xor_sync(~0u, ts1, 2);
        l0 = l0 * sc0 + ts0;
        l1 = l1 * sc1 + ts1;
        #pragma unroll
        for (int nt = 0; nt < 8; nt++) {
            Oacc[nt][0] *= sc0; Oacc[nt][1] *= sc0;
            Oacc[nt][2] *= sc1; Oacc[nt][3] *= sc1;
        }

        #pragma unroll
        for (int kc = 0; kc < 4; kc++) {
            uint32_t vb[8][2];
            #pragma unroll
            for (int nt = 0; nt < 8; nt++) {
                const __half* pv = Vb + (nt * 8 + (lane >> 2)) * 72 + kc * 16 + ccol;
                vb[nt][0] = *(const uint32_t*)pv;
                vb[nt][1] = *(const uint32_t*)(pv + 8);
            }
            uint32_t af[4] = {ph[2*kc][0], ph[2*kc][1], ph[2*kc+1][0], ph[2*kc+1][1]};
            #pragma unroll
            for (int nt = 0; nt < 8; nt++)
                mma_f16(Oacc[nt], af, vb[nt]);
        }
    }

    const int b = z / H_, h = z % H_;
    float inv0 = SCALE_INV / l0, inv1 = SCALE_INV / l1;
    size_t s0 = (size_t)(b * S_ + q0 + r0) * E_ + h * 64 + ccol;
    size_t s1 = (size_t)(b * S_ + q0 + r0 + 8) * E_ + h * 64 + ccol;
    #pragma unroll
    for (int nt = 0; nt < 8; nt++) {
        *(__half2*)&merged[s0 + nt * 8] =
            __floats2half2_rn(Oacc[nt][0] * inv0, Oacc[nt][1] * inv0);
        *(__half2*)&merged[s1 + nt * 8] =
            __floats2half2_rn(Oacc[nt][2] * inv1, Oacc[nt][3] * inv1);
    }
}

// ---------------- block reductions ----------------
__device__ __forceinline__ float block_reduce(float v) {
    __shared__ float sh[8];
    int lane = threadIdx.x & 31, wid = threadIdx.x >> 5;
    #pragma unroll
    for (int o = 16; o; o >>= 1) v += __shfl_xor_sync(0xffffffffu, v, o);
    if (lane == 0) sh[wid] = v;
    __syncthreads();
    if (wid == 0) {
        v = (lane < 8) ? sh[lane] : 0.0f;
        #pragma unroll
        for (int o = 4; o; o >>= 1) v += __shfl_xor_sync(0xffffffffu, v, o);
        if (lane == 0) sh[0] = v;
    }
    __syncthreads();
    float r = sh[0];
    __syncthreads();
    return r;
}

__global__ __launch_bounds__(256) void ln_kernel(
    const float* __restrict__ in, const float* __restrict__ g,
    const float* __restrict__ bb, __half* __restrict__ out)
{
    long long base = (long long)blockIdx.x * E_;
    int t = threadIdx.x;
    float v[3];
    #pragma unroll
    for (int i = 0; i < 3; i++) v[i] = in[base + t + i*256];
    float s  = block_reduce(v[0] + v[1] + v[2]);
    float sq = block_reduce(v[0]*v[0] + v[1]*v[1] + v[2]*v[2]);
    float mean = s * (1.0f/E_);
    float rstd = rsqrtf(sq * (1.0f/E_) - mean*mean + 1e-5f);
    #pragma unroll
    for (int i = 0; i < 3; i++) {
        int c = t + i*256;
        out[base + c] = __float2half_rn((v[i] - mean) * rstd * g[c] + bb[c]);
    }
}

// in = p0 + p1 (split-K partials)
__global__ __launch_bounds__(256) void ln2_ln3_kernel(
    const float* __restrict__ p0, const float* __restrict__ p1,
    const float* __restrict__ x,
    const float* __restrict__ g2, const float* __restrict__ b2,
    const float* __restrict__ g3, const float* __restrict__ b3,
    float* __restrict__ r1, __half* __restrict__ f)
{
    long long base = (long long)blockIdx.x * E_;
    int t = threadIdx.x;
    float v[3];
    #pragma unroll
    for (int i = 0; i < 3; i++) v[i] = p0[base + t + i*256] + p1[base + t + i*256];
    float s  = block_reduce(v[0] + v[1] + v[2]);
    float sq = block_reduce(v[0]*v[0] + v[1]*v[1] + v[2]*v[2]);
    float mean = s * (1.0f/E_);
    float rstd = rsqrtf(sq * (1.0f/E_) - mean*mean + 1e-5f);
    #pragma unroll
    for (int i = 0; i < 3; i++) {
        int c = t + i*256;
        v[i] = (v[i] - mean) * rstd * g2[c] + b2[c] + x[base + c];
        r1[base + c] = v[i];
    }
    float s2  = block_reduce(v[0] + v[1] + v[2]);
    float sq2 = block_reduce(v[0]*v[0] + v[1]*v[1] + v[2]*v[2]);
    float mean2 = s2 * (1.0f/E_);
    float rstd2 = rsqrtf(sq2 * (1.0f/E_) - mean2*mean2 + 1e-5f);
    #pragma unroll
    for (int i = 0; i < 3; i++) {
        int c = t + i*256;
        f[base + c] = __float2half_rn((v[i] - mean2) * rstd2 * g3[c] + b3[c]);
    }
}

// f2 = p0 + p1 (split-K partials)
__global__ __launch_bounds__(256) void ln4_ln1_kernel(
    const float* __restrict__ p0, const float* __restrict__ p1,
    const float* __restrict__ r1, const float* __restrict__ x,
    const float* __restrict__ g4, const float* __restrict__ b4,
    const float* __restrict__ g1, const float* __restrict__ b1,
    float* __restrict__ xout, __half* __restrict__ hout)
{
    long long base = (long long)blockIdx.x * E_;
    int t = threadIdx.x;
    float v[3];
    #pragma unroll
    for (int i = 0; i < 3; i++) v[i] = p0[base + t + i*256] + p1[base + t + i*256];
    float s  = block_reduce(v[0] + v[1] + v[2]);
    float sq = block_reduce(v[0]*v[0] + v[1]*v[1] + v[2]*v[2]);
    float mean = s * (1.0f/E_);
    float rstd = rsqrtf(sq * (1.0f/E_) - mean*mean + 1e-5f);
    #pragma unroll
    for (int i = 0; i < 3; i++) {
        int c = t + i*256;
        v[i] = (v[i] - mean) * rstd * g4[c] + b4[c] + r1[base + c] + x[base + c];
        xout[base + c] = v[i];
    }
    if (g1 == nullptr) return;
    float s2  = block_reduce(v[0] + v[1] + v[2]);
    float sq2 = block_reduce(v[0]*v[0] + v[1]*v[1] + v[2]*v[2]);
    float mean2 = s2 * (1.0f/E_);
    float rstd2 = rsqrtf(sq2 * (1.0f/E_) - mean2*mean2 + 1e-5f);
    #pragma unroll
    for (int i = 0; i < 3; i++) {
        int c = t + i*256;
        hout[base + c] = __float2half_rn((v[i] - mean2) * rstd2 * g1[c] + b1[c]);
    }
}

// -------- weight transpose + halve: in [L][K][N] f32 -> out [L][N][K] half --
__global__ __launch_bounds__(256) void transpose_h(
    const float* __restrict__ in, __half* __restrict__ out, int K, int N)
{
    __shared__ float t[32][33];
    size_t lofs = (size_t)blockIdx.z * K * N;
    in += lofs; out += lofs;
    int n0 = blockIdx.x * 32, k0 = blockIdx.y * 32;
    int tx = threadIdx.x & 31, ty = threadIdx.x >> 5;   // 32 x 8
    #pragma unroll
    for (int i = 0; i < 4; i++)
        t[ty + i*8][tx] = in[(size_t)(k0 + ty + i*8) * N + n0 + tx];
    __syncthreads();
    #pragma unroll
    for (int i = 0; i < 4; i++)
        out[(size_t)(n0 + ty + i*8) * K + k0 + tx] = __float2half_rn(t[tx][ty + i*8]);
}

// -------- qkv weight transpose with column permutation ----------------------
__global__ __launch_bounds__(256) void transpose_qkv(
    const float* __restrict__ in, __half* __restrict__ out)
{
    __shared__ float t[32][33];
    size_t lofs = (size_t)blockIdx.z * E_ * E3_;
    in += lofs; out += lofs;
    int n0 = blockIdx.x * 32, k0 = blockIdx.y * 32;
    int tx = threadIdx.x & 31, ty = threadIdx.x >> 5;
    int c_reg = n0 / E_;
    #pragma unroll
    for (int i = 0; i < 4; i++) {
        int nn = n0 + tx;
        int n_orig = (nn % E_) * 3 + c_reg;
        t[ty + i*8][tx] = in[(size_t)(k0 + ty + i*8) * E3_ + n_orig];
    }
    __syncthreads();
    #pragma unroll
    for (int i = 0; i < 4; i++)
        out[(size_t)(n0 + ty + i*8) * E_ + k0 + tx] = __float2half_rn(t[tx][ty + i*8]);
}

__global__ __launch_bounds__(256) void permute_bias(
    const float* __restrict__ in, float* __restrict__ out)
{
    int i = blockIdx.x * 256 + threadIdx.x;
    int l = i / E3_, n = i % E3_;
    int n_orig = (n % E_) * 3 + n / E_;
    out[i] = in[l * E3_ + n_orig];
}

// ---------------- host orchestration ----------------
extern "C" void kernel_launch(void* const* d_in, const int* in_sizes, int n_in,
                              void* d_out, int out_size)
{
    (void)in_sizes; (void)n_in; (void)out_size;

    const float* x_in  = (const float*)d_in[0];
    const float* Wqkv  = (const float*)d_in[1];
    const float* bqkv  = (const float*)d_in[2];
    const float* Wp    = (const float*)d_in[3];
    const float* bp    = (const float*)d_in[4];
    const float* W1    = (const float*)d_in[5];
    const float* b1    = (const float*)d_in[6];
    const float* W2    = (const float*)d_in[7];
    const float* b2    = (const float*)d_in[8];
    const float* g1    = (const float*)d_in[9];
    const float* be1   = (const float*)d_in[10];
    const float* g2    = (const float*)d_in[11];
    const float* be2   = (const float*)d_in[12];
    const float* g3    = (const float*)d_in[13];
    const float* be3   = (const float*)d_in[14];
    const float* g4    = (const float*)d_in[15];
    const float* be4   = (const float*)d_in[16];

    static bool attr_done = false;
    if (!attr_done) {
        cudaFuncSetAttribute(gemm_h<0>,
                             cudaFuncAttributeMaxDynamicSharedMemorySize, GH_SMEM);
        cudaFuncSetAttribute(gemm_h<1>,
                             cudaFuncAttributeMaxDynamicSharedMemorySize, GH_SMEM);
        cudaFuncSetAttribute(gemm_h<2>,
                             cudaFuncAttributeMaxDynamicSharedMemorySize, GH_SMEM);
        cudaFuncSetAttribute(flash2_kernel,
                             cudaFuncAttributeMaxDynamicSharedMemorySize, FA2_SMEM);
        attr_done = true;
    }

    __half *p_h, *p_q, *p_k, *p_v, *p_merged, *p_f, *p_ff;
    float *p_oproj, *p_r1, *p_f2, *p_x, *p_bqkv;
    __half *w_qkv, *w_p, *w_1, *w_2;
    cudaGetSymbolAddress((void**)&p_h, g_h);
    cudaGetSymbolAddress((void**)&p_q, g_q);
    cudaGetSymbolAddress((void**)&p_k, g_k);
    cudaGetSymbolAddress((void**)&p_v, g_v);
    cudaGetSymbolAddress((void**)&p_merged, g_merged);
    cudaGetSymbolAddress((void**)&p_oproj, g_oproj);
    cudaGetSymbolAddress((void**)&p_r1, g_r1);
    cudaGetSymbolAddress((void**)&p_f, g_f);
    cudaGetSymbolAddress((void**)&p_ff, g_ff);
    cudaGetSymbolAddress((void**)&p_f2, g_f2);
    cudaGetSymbolAddress((void**)&p_x, g_x);
    cudaGetSymbolAddress((void**)&p_bqkv, g_bqkv_p);
    cudaGetSymbolAddress((void**)&w_qkv, g_Wqkv_t);
    cudaGetSymbolAddress((void**)&w_p, g_Wp_t);
    cudaGetSymbolAddress((void**)&w_1, g_W1_t);
    cudaGetSymbolAddress((void**)&w_2, g_W2_t);

    // pre-transpose + halve all weights (once per launch)
    transpose_qkv<<<dim3(E3_/32, E_/32, L_), 256>>>(Wqkv, w_qkv);
    permute_bias<<<(L_*E3_)/256, 256>>>(bqkv, p_bqkv);
    transpose_h<<<dim3(E_/32,  E_/32, L_), 256>>>(Wp,   w_p,   E_, E_);
    transpose_h<<<dim3(FF_/32, E_/32, L_), 256>>>(W1,   w_1,   E_, FF_);
    transpose_h<<<dim3(E_/32, FF_/32, L_), 256>>>(W2,   w_2,   FF_, E_);

    cudaMemcpyAsync(p_x, x_in, (size_t)NTOK * E_ * sizeof(float),
                    cudaMemcpyDeviceToDevice, 0);

    // h = LN1_0(x)
    ln_kernel<<<NTOK, 256>>>(p_x, g1, be1, p_h);

    const size_t PSZ = (size_t)NTOK * E_;   // partial-buffer stride

    for (int l = 0; l < L_; ++l) {
        const __half* Wqkv_l = w_qkv + (size_t)l * E_ * E3_;
        const float*  bqkv_l = p_bqkv + (size_t)l * E3_;
        const __half* Wp_l   = w_p  + (size_t)l * E_ * E_;
        const float*  bp_l   = bp   + (size_t)l * E_;
        const __half* W1_l   = w_1  + (size_t)l * E_ * FF_;
        const float*  b1_l   = b1   + (size_t)l * FF_;
        const __half* W2_l   = w_2  + (size_t)l * FF_ * E_;
        const float*  b2_l   = b2   + (size_t)l * E_;
        const float* g2_l = g2 + (size_t)l * E_, *be2_l = be2 + (size_t)l * E_;
        const float* g3_l = g3 + (size_t)l * E_, *be3_l = be3 + (size_t)l * E_;
        const float* g4_l = g4 + (size_t)l * E_, *be4_l = be4 + (size_t)l * E_;

        // qkv = h @ Wqkv_perm + bqkv_perm -> q | k | v regions (half)
        gemm_h<2><<<dim3(E3_/128, NTOK/128, 1), 256, GH_SMEM>>>(
            p_h, Wqkv_l, bqkv_l, nullptr, NTOK, E3_, E_, E_, p_q, p_k, p_v);
        // fused flash attention (online softmax) -> merged (half)
        flash2_kernel<<<dim3(S_/64, BH), 128, FA2_SMEM>>>(p_q, p_k, p_v, p_merged);
        // oproj partials = merged @ Wp (+bp on z=0), split-K=2 -> 192 CTAs
        gemm_h<0><<<dim3(E_/128, NTOK/128, 2), 256, GH_SMEM>>>(
            p_merged, Wp_l, bp_l, p_oproj, NTOK, E_, E_/2, E_,
            nullptr, nullptr, nullptr);
        // r1 = LN2(oproj0+oproj1) + x ; f = LN3(r1) (half)
        ln2_ln3_kernel<<<NTOK, 256>>>(p_oproj, p_oproj + PSZ, p_x,
                                      g2_l, be2_l, g3_l, be3_l, p_r1, p_f);
        // ff = gelu(f @ W1 + b1) (half)
        gemm_h<1><<<dim3(FF_/128, NTOK/128, 1), 256, GH_SMEM>>>(
            p_f, W1_l, b1_l, p_ff, NTOK, FF_, E_, E_, nullptr, nullptr, nullptr);
        // f2 partials = ff @ W2 (+b2 on z=0), split-K=2 -> 192 CTAs
        gemm_h<0><<<dim3(E_/128, NTOK/128, 2), 256, GH_SMEM>>>(
            p_ff, W2_l, b2_l, p_f2, NTOK, E_, FF_/2, FF_,
            nullptr, nullptr, nullptr);
        // x = LN4(f20+f21) + r1 + x ; h = LN1_{l+1}(x) (half)
        const float* g1n  = (l + 1 < L_) ? g1  + (size_t)(l + 1) * E_ : nullptr;
        const float* be1n = (l + 1 < L_) ? be1 + (size_t)(l + 1) * E_ : nullptr;
        ln4_ln1_kernel<<<NTOK, 256>>>(p_f2, p_f2 + PSZ, p_r1, p_x,
                                      g4_l, be4_l, g1n, be1n, p_x, p_h);
    }

    cudaMemcpyAsync(d_out, p_x, (size_t)NTOK * E_ * sizeof(float),
                    cudaMemcpyDeviceToDevice, 0);
}